// round 7
// baseline (speedup 1.0000x reference)
#include <cuda_runtime.h>
#include <cstdint>
#include <cstddef>

// ---------------------------------------------------------------------------
// GraphSAGE 2-layer (N=100000, E=800000, 128 -> 128 -> 47, fp32):
//   adjacency build -> gather-mean -> GEMM1(persistent, weight-resident,
//   FFMA2, +bias+L2norm+BN stats) -> BN finalize -> gather-mean(+BN+ReLU
//   fused) -> GEMM2(weight-resident, +BN self-term, +bias+L2norm) -> out
// ---------------------------------------------------------------------------

#define NMAX 100000
#define CH   128
#define KC   32          // K-chunk for GEMM input staging
#define ASTR 36          // inS row stride (KC + 4 pad)
#define SLOTS 64         // max neighbors stored per node (P(overflow) ~ 0)

typedef unsigned long long u64;

__device__ __align__(16) float g_agg[(size_t)NMAX * CH];
__device__ __align__(16) float g_h[(size_t)NMAX * CH];
__device__ __align__(16) int   g_cnt[NMAX];
__device__ __align__(16) int   g_slot[(size_t)NMAX * SLOTS];
__device__ __align__(16) float g_wT1[256 * 128];   // [k][c]
__device__ __align__(16) float g_wT2[256 * 48];    // [k][c] (c padded to 48)
__device__ __align__(16) float g_bnsum[128];
__device__ __align__(16) float g_bnsq[128];
__device__ __align__(16) float g_bnscale[128];
__device__ __align__(16) float g_bnshift[128];
__device__ int g_ei32;

// ---- f32x2 packed helpers --------------------------------------------------
__device__ __forceinline__ void ffma2(u64& acc, u64 a, u64 b) {
    asm("fma.rn.f32x2 %0, %1, %2, %0;" : "+l"(acc) : "l"(a), "l"(b));
}
__device__ __forceinline__ u64 pack2(float x, float y) {
    u64 r;
    asm("mov.b64 %0, {%1, %2};" : "=l"(r) : "f"(x), "f"(y));
    return r;
}
__device__ __forceinline__ float2 unpack2(u64 v) {
    float2 r;
    asm("mov.b64 {%0, %1}, %2;" : "=f"(r.x), "=f"(r.y) : "l"(v));
    return r;
}

// ---------------------------------------------------------------------------
__global__ void detect_ei(const void* ei, int Nn) {
    int lane = threadIdx.x & 31;
    long long v = ((const long long*)ei)[lane & 15];
    unsigned bad = __ballot_sync(0xffffffffu, v < 0 || v >= (long long)Nn);
    if (lane == 0 && blockIdx.x == 0) g_ei32 = bad ? 1 : 0;
}

__global__ void zero_small(int Nn) {
    int i = blockIdx.x * blockDim.x + threadIdx.x;
    int stride = gridDim.x * blockDim.x;
    for (int j = i; j < Nn; j += stride) g_cnt[j] = 0;
    if (i < 128) { g_bnsum[i] = 0.f; g_bnsq[i] = 0.f; }
}

__global__ void prep_weights(const float* __restrict__ w1l, const float* __restrict__ w1r,
                             const float* __restrict__ w2l, const float* __restrict__ w2r) {
    int t = blockIdx.x * blockDim.x + threadIdx.x;
    if (t < 256 * 128) {
        int k = t >> 7, c = t & 127;
        g_wT1[t] = (k < 128) ? w1l[c * 128 + k] : w1r[c * 128 + (k - 128)];
    }
    if (t < 256 * 48) {
        int k = t / 48, c = t - k * 48;
        float v = 0.f;
        if (c < 47) v = (k < 128) ? w2l[c * 128 + k] : w2r[c * 128 + (k - 128)];
        g_wT2[t] = v;
    }
}

__global__ void __launch_bounds__(256) build_adj(
    const void* __restrict__ ei, int E, int Nn)
{
    const int is32 = g_ei32;
    int t = blockIdx.x * blockDim.x + threadIdx.x;
    int stride = gridDim.x * blockDim.x;
    for (int e = t; e < E; e += stride) {
        int src, dst;
        if (is32) {
            src = ((const int*)ei)[e];
            dst = ((const int*)ei)[(size_t)E + e];
        } else {
            src = (int)((const long long*)ei)[e];
            dst = (int)((const long long*)ei)[(size_t)E + e];
        }
        if ((unsigned)src >= (unsigned)Nn || (unsigned)dst >= (unsigned)Nn) continue;
        int pos = atomicAdd(&g_cnt[dst], 1);
        if (pos < SLOTS) g_slot[(size_t)dst * SLOTS + pos] = src;
    }
}

// Gather-mean: one warp per node; lane l owns columns {l, l+32, l+64, l+96}.
// withBN: source features are pre-BN h; apply relu(h*sc+sh) on the fly.
__global__ void __launch_bounds__(256) gather_mean(
    const float* __restrict__ feat, int withBN, int Nn)
{
    if (withBN) feat = (const float*)g_h;
    int gw   = (blockIdx.x * blockDim.x + threadIdx.x) >> 5;
    int lane = threadIdx.x & 31;
    int nw   = (gridDim.x * blockDim.x) >> 5;
    float sc0 = 1.f, sc1 = 1.f, sc2 = 1.f, sc3 = 1.f;
    float sh0 = 0.f, sh1 = 0.f, sh2 = 0.f, sh3 = 0.f;
    if (withBN) {
        sc0 = g_bnscale[lane];      sh0 = g_bnshift[lane];
        sc1 = g_bnscale[lane + 32]; sh1 = g_bnshift[lane + 32];
        sc2 = g_bnscale[lane + 64]; sh2 = g_bnshift[lane + 64];
        sc3 = g_bnscale[lane + 96]; sh3 = g_bnshift[lane + 96];
    }
    for (int n = gw; n < Nn; n += nw) {
        int cnt = g_cnt[n];
        int m = min(cnt, SLOTS);
        const int* sl = g_slot + (size_t)n * SLOTS;
        float a0 = 0.f, a1 = 0.f, a2 = 0.f, a3 = 0.f;
        if (withBN) {
            for (int j = 0; j < m; j++) {
                const float* p = feat + (size_t)sl[j] * 128 + lane;
                a0 += fmaxf(fmaf(p[0],  sc0, sh0), 0.f);
                a1 += fmaxf(fmaf(p[32], sc1, sh1), 0.f);
                a2 += fmaxf(fmaf(p[64], sc2, sh2), 0.f);
                a3 += fmaxf(fmaf(p[96], sc3, sh3), 0.f);
            }
        } else {
            int j = 0;
            for (; j + 2 <= m; j += 2) {
                int s0 = sl[j], s1 = sl[j + 1];
                const float* p0 = feat + (size_t)s0 * 128 + lane;
                const float* p1 = feat + (size_t)s1 * 128 + lane;
                a0 += p0[0] + p1[0];
                a1 += p0[32] + p1[32];
                a2 += p0[64] + p1[64];
                a3 += p0[96] + p1[96];
            }
            if (j < m) {
                const float* p0 = feat + (size_t)sl[j] * 128 + lane;
                a0 += p0[0]; a1 += p0[32]; a2 += p0[64]; a3 += p0[96];
            }
        }
        float r = 1.f / fmaxf((float)cnt, 1.f);
        float* dp = g_agg + (size_t)n * 128 + lane;
        dp[0]  = a0 * r;
        dp[32] = a1 * r;
        dp[64] = a2 * r;
        dp[96] = a3 * r;
    }
}

// ---------------------------------------------------------------------------
// GEMM1 (persistent, weight-resident): h[n,c] = L2norm_row([agg|x] @ wT1 + b1l)
// 256 threads; tile 128 nodes x 128 channels; per thread 4 nodes x 16 ch.
// Weights (256x128 = 128KB) resident in dynamic smem. Fused BN sum/sumsq.
// ---------------------------------------------------------------------------
__global__ void __launch_bounds__(256) sage_gemm1(
    const float* __restrict__ xin, const float* __restrict__ bias, int Nn)
{
    extern __shared__ float wS[];          // 256*128 floats = 128 KB (dynamic)
    __shared__ float inS[128 * ASTR];      // 18 KB
    __shared__ float bnstage[2][8][128];   // 8 KB

    const int tid = threadIdx.x;
    const int ng = tid >> 3, cg = tid & 7;

    {   // load full weight matrix once
        const float4* wsrc = (const float4*)g_wT1;
        float4* wdst = (float4*)wS;
        for (int i4 = tid; i4 < 256 * 32; i4 += 256) wdst[i4] = wsrc[i4];
    }

    float2 bp[8];
#pragma unroll
    for (int p = 0; p < 8; p++) {
        int c = (p >> 1) * 32 + cg * 4 + (p & 1) * 2;
        bp[p] = *(const float2*)&bias[c];
    }

    float2 s1[8], s2[8];
#pragma unroll
    for (int p = 0; p < 8; p++) { s1[p] = make_float2(0.f, 0.f); s2[p] = make_float2(0.f, 0.f); }
    __syncthreads();

    for (int base = blockIdx.x * 128; base < Nn; base += gridDim.x * 128) {
        int nrem = min(128, Nn - base);

        u64 acc[4][8];
#pragma unroll
        for (int i = 0; i < 4; i++)
#pragma unroll
            for (int p = 0; p < 8; p++) acc[i][p] = 0ull;

        for (int kc = 0; kc < 8; kc++) {
            __syncthreads();
            for (int i4 = tid; i4 < 128 * (KC / 4); i4 += 256) {
                int n = i4 >> 3;
                int kq = (i4 & 7) << 2;
                int k = kc * KC + kq;
                float4 v = make_float4(0.f, 0.f, 0.f, 0.f);
                if (n < nrem) {
                    if (k < 128) v = *(const float4*)&g_agg[(size_t)(base + n) * 128 + k];
                    else         v = *(const float4*)&xin[(size_t)(base + n) * 128 + (k - 128)];
                }
                *(float4*)&inS[n * ASTR + kq] = v;
            }
            __syncthreads();

#pragma unroll 4
            for (int kk = 0; kk < KC; kk++) {
                const ulonglong2* wrow = (const ulonglong2*)&wS[(kc * KC + kk) * 128];
                ulonglong2 w0 = wrow[cg];
                ulonglong2 w1 = wrow[cg + 8];
                ulonglong2 w2 = wrow[cg + 16];
                ulonglong2 w3 = wrow[cg + 24];
#pragma unroll
                for (int i = 0; i < 4; i++) {
                    float a = inS[(ng * 4 + i) * ASTR + kk];
                    u64 aa = pack2(a, a);
                    ffma2(acc[i][0], aa, w0.x);
                    ffma2(acc[i][1], aa, w0.y);
                    ffma2(acc[i][2], aa, w1.x);
                    ffma2(acc[i][3], aa, w1.y);
                    ffma2(acc[i][4], aa, w2.x);
                    ffma2(acc[i][5], aa, w2.y);
                    ffma2(acc[i][6], aa, w3.x);
                    ffma2(acc[i][7], aa, w3.y);
                }
            }
        }

        // Epilogue: bias, row L2 norm, store h (pre-BN), BN partials
#pragma unroll
        for (int i = 0; i < 4; i++) {
            float2 v[8];
            float ss = 0.f;
#pragma unroll
            for (int p = 0; p < 8; p++) {
                v[p] = unpack2(acc[i][p]);
                v[p].x += bp[p].x; v[p].y += bp[p].y;
                ss += v[p].x * v[p].x + v[p].y * v[p].y;
            }
            ss += __shfl_xor_sync(0xffffffffu, ss, 1);
            ss += __shfl_xor_sync(0xffffffffu, ss, 2);
            ss += __shfl_xor_sync(0xffffffffu, ss, 4);
            float inv = 1.f / fmaxf(sqrtf(ss), 1e-12f);
            int nl = ng * 4 + i;
            if (nl < nrem) {
                size_t n = (size_t)(base + nl);
#pragma unroll
                for (int m = 0; m < 4; m++) {
                    float2 r0 = v[2 * m], r1 = v[2 * m + 1];
                    float4 r;
                    r.x = r0.x * inv; r.y = r0.y * inv;
                    r.z = r1.x * inv; r.w = r1.y * inv;
                    *(float4*)&g_h[n * 128 + m * 32 + cg * 4] = r;
                    s1[2 * m].x += r.x;     s1[2 * m].y += r.y;
                    s1[2 * m + 1].x += r.z; s1[2 * m + 1].y += r.w;
                    s2[2 * m].x += r.x * r.x;     s2[2 * m].y += r.y * r.y;
                    s2[2 * m + 1].x += r.z * r.z; s2[2 * m + 1].y += r.w * r.w;
                }
            }
        }
        __syncthreads();
    }

    // BN partial reduction: shuffle over node-groups, stage via smem, 1 atomic/channel.
#pragma unroll
    for (int off = 8; off < 32; off <<= 1) {
#pragma unroll
        for (int p = 0; p < 8; p++) {
            s1[p].x += __shfl_xor_sync(0xffffffffu, s1[p].x, off);
            s1[p].y += __shfl_xor_sync(0xffffffffu, s1[p].y, off);
            s2[p].x += __shfl_xor_sync(0xffffffffu, s2[p].x, off);
            s2[p].y += __shfl_xor_sync(0xffffffffu, s2[p].y, off);
        }
    }
    int warp = tid >> 5, lane = tid & 31;
    if (lane < 8) {
#pragma unroll
        for (int p = 0; p < 8; p++) {
            int c = (p >> 1) * 32 + lane * 4 + (p & 1) * 2;
            bnstage[0][warp][c] = s1[p].x; bnstage[0][warp][c + 1] = s1[p].y;
            bnstage[1][warp][c] = s2[p].x; bnstage[1][warp][c + 1] = s2[p].y;
        }
    }
    __syncthreads();
    if (tid < 128) {
        float a0 = 0.f, a1 = 0.f;
#pragma unroll
        for (int w = 0; w < 8; w++) { a0 += bnstage[0][w][tid]; a1 += bnstage[1][w][tid]; }
        atomicAdd(&g_bnsum[tid], a0);
        atomicAdd(&g_bnsq[tid], a1);
    }
}

__global__ void bn_finalize(const float* __restrict__ gamma, const float* __restrict__ beta, float invN) {
    int c = threadIdx.x;
    float mean = g_bnsum[c] * invN;
    float var = g_bnsq[c] * invN - mean * mean;
    float sc = gamma[c] * rsqrtf(var + 1e-5f);
    g_bnscale[c] = sc;
    g_bnshift[c] = beta[c] - mean * sc;
}

// ---------------------------------------------------------------------------
// GEMM2 (weight-resident): out[n,c<47] = L2norm_row([agg2 | relu(bn(h))] @ wT2 + b2l)
// 256 threads; tile 128 nodes; per thread 4 nodes x 3 channel pairs.
// Self-term BN+ReLU applied during staging.
// ---------------------------------------------------------------------------
__global__ void __launch_bounds__(256) sage_gemm2(
    const float* __restrict__ b2l, float* __restrict__ outp, int Nn)
{
    extern __shared__ float wS[];        // 256*48 floats = 48 KB (dynamic)
    __shared__ float inS[128 * ASTR];    // 18 KB

    const int tid = threadIdx.x;
    const int ng = tid >> 3, cg = tid & 7;

    {
        const float4* wsrc = (const float4*)g_wT2;
        float4* wdst = (float4*)wS;
        for (int i4 = tid; i4 < 256 * 12; i4 += 256) wdst[i4] = wsrc[i4];
    }

    float2 b2[3];
#pragma unroll
    for (int m = 0; m < 3; m++) {
        int c = m * 16 + cg * 2;
        b2[m].x = (c < 47) ? b2l[c] : 0.f;
        b2[m].y = (c + 1 < 47) ? b2l[c + 1] : 0.f;
    }
    __syncthreads();

    for (int base = blockIdx.x * 128; base < Nn; base += gridDim.x * 128) {
        int nrem = min(128, Nn - base);

        u64 acc[4][3];
#pragma unroll
        for (int i = 0; i < 4; i++)
#pragma unroll
            for (int m = 0; m < 3; m++) acc[i][m] = 0ull;

        for (int kc = 0; kc < 8; kc++) {
            __syncthreads();
            for (int i4 = tid; i4 < 128 * (KC / 4); i4 += 256) {
                int n = i4 >> 3;
                int kq = (i4 & 7) << 2;
                int k = kc * KC + kq;
                float4 v = make_float4(0.f, 0.f, 0.f, 0.f);
                if (n < nrem) {
                    if (k < 128) {
                        v = *(const float4*)&g_agg[(size_t)(base + n) * 128 + k];
                    } else {
                        int c = k - 128;
                        v = *(const float4*)&g_h[(size_t)(base + n) * 128 + c];
                        float4 sc = *(const float4*)&g_bnscale[c];
                        float4 sh = *(const float4*)&g_bnshift[c];
                        v.x = fmaxf(fmaf(v.x, sc.x, sh.x), 0.f);
                        v.y = fmaxf(fmaf(v.y, sc.y, sh.y), 0.f);
                        v.z = fmaxf(fmaf(v.z, sc.z, sh.z), 0.f);
                        v.w = fmaxf(fmaf(v.w, sc.w, sh.w), 0.f);
                    }
                }
                *(float4*)&inS[n * ASTR + kq] = v;
            }
            __syncthreads();

#pragma unroll 4
            for (int kk = 0; kk < KC; kk++) {
                const float* wrow = &wS[(kc * KC + kk) * 48];
                u64 w0 = *(const u64*)&wrow[cg * 2];
                u64 w1 = *(const u64*)&wrow[16 + cg * 2];
                u64 w2 = *(const u64*)&wrow[32 + cg * 2];
#pragma unroll
                for (int i = 0; i < 4; i++) {
                    float a = inS[(ng * 4 + i) * ASTR + kk];
                    u64 aa = pack2(a, a);
                    ffma2(acc[i][0], aa, w0);
                    ffma2(acc[i][1], aa, w1);
                    ffma2(acc[i][2], aa, w2);
                }
            }
        }

#pragma unroll
        for (int i = 0; i < 4; i++) {
            float2 v[3];
            float ss = 0.f;
#pragma unroll
            for (int m = 0; m < 3; m++) {
                v[m] = unpack2(acc[i][m]);
                v[m].x += b2[m].x; v[m].y += b2[m].y;
                ss += v[m].x * v[m].x + v[m].y * v[m].y;
            }
            ss += __shfl_xor_sync(0xffffffffu, ss, 1);
            ss += __shfl_xor_sync(0xffffffffu, ss, 2);
            ss += __shfl_xor_sync(0xffffffffu, ss, 4);
            float inv = 1.f / fmaxf(sqrtf(ss), 1e-12f);
            int nl = ng * 4 + i;
            if (nl < nrem) {
                size_t n = (size_t)(base + nl);
#pragma unroll
                for (int m = 0; m < 3; m++) {
                    int c0 = m * 16 + cg * 2;
                    outp[n * 47 + c0] = v[m].x * inv;
                    if (c0 + 1 < 47) outp[n * 47 + c0 + 1] = v[m].y * inv;
                }
            }
        }
        __syncthreads();
    }
}

// ---------------------------------------------------------------------------
extern "C" void kernel_launch(void* const* d_in, const int* in_sizes, int n_in,
                              void* d_out, int out_size) {
    const float* x     = (const float*)d_in[0];
    const void*  ei    = d_in[1];
    const float* w1l   = (const float*)d_in[2];
    const float* b1l   = (const float*)d_in[3];
    const float* w1r   = (const float*)d_in[4];
    const float* gamma = (const float*)d_in[5];
    const float* beta  = (const float*)d_in[6];
    const float* w2l   = (const float*)d_in[7];
    const float* b2l   = (const float*)d_in[8];
    const float* w2r   = (const float*)d_in[9];
    int Nn = in_sizes[0] / 128;
    int E  = in_sizes[1] / 2;

    static int attr_done = 0;
    if (!attr_done) {
        cudaFuncSetAttribute(sage_gemm1, cudaFuncAttributeMaxDynamicSharedMemorySize, 131072);
        cudaFuncSetAttribute(sage_gemm2, cudaFuncAttributeMaxDynamicSharedMemorySize, 49152);
        attr_done = 1;
    }

    detect_ei<<<1, 32>>>(ei, Nn);
    zero_small<<<256, 256>>>(Nn);
    prep_weights<<<(256 * 128 + 255) / 256, 256>>>(w1l, w1r, w2l, w2r);
    build_adj<<<(E + 255) / 256, 256>>>(ei, E, Nn);
    gather_mean<<<2048, 256>>>(x, 0, Nn);
    sage_gemm1<<<148, 256, 131072>>>(x, b1l, Nn);
    bn_finalize<<<1, 128>>>(gamma, beta, 1.0f / (float)Nn);
    gather_mean<<<2048, 256>>>(nullptr, 1, Nn);
    sage_gemm2<<<296, 256, 49152>>>(b2l, (float*)d_out, Nn);
}

// round 8
// speedup vs baseline: 1.2397x; 1.2397x over previous
#include <cuda_runtime.h>
#include <cstdint>
#include <cstddef>

// ---------------------------------------------------------------------------
// GraphSAGE 2-layer (N=100000, E=800000, 128 -> 128 -> 47, fp32):
//   adjacency build -> gather-mean -> GEMM1(FFMA2, +bias+L2norm+BN stats)
//   -> BN finalize -> gather-mean(+BN+ReLU fused) -> GEMM2(+BN self-term,
//   +bias+L2norm) -> out
// R6 champion tiling (128-thread GEMM blocks, KC-streamed weights, high
// occupancy) + BN fusion into consumers; no separate bn_apply pass.
// ---------------------------------------------------------------------------

#define NMAX 100000
#define CH   128
#define KC   32          // K-chunk for GEMMs
#define ASTR 36          // inS row stride (KC + 4 pad)
#define SLOTS 64         // max neighbors stored per node (P(overflow) ~ 0)

typedef unsigned long long u64;

__device__ __align__(16) float g_agg[(size_t)NMAX * CH];
__device__ __align__(16) float g_h[(size_t)NMAX * CH];
__device__ __align__(16) int   g_cnt[NMAX];
__device__ __align__(16) int   g_slot[(size_t)NMAX * SLOTS];
__device__ __align__(16) float g_wT1[256 * 128];   // [k][c]
__device__ __align__(16) float g_wT2[256 * 48];    // [k][c] (c padded to 48)
__device__ __align__(16) float g_bnsum[128];
__device__ __align__(16) float g_bnsq[128];
__device__ __align__(16) float g_bnscale[128];
__device__ __align__(16) float g_bnshift[128];
__device__ int g_ei32;

// ---- f32x2 packed helpers --------------------------------------------------
__device__ __forceinline__ void ffma2(u64& acc, u64 a, u64 b) {
    asm("fma.rn.f32x2 %0, %1, %2, %0;" : "+l"(acc) : "l"(a), "l"(b));
}
__device__ __forceinline__ u64 pack2(float x, float y) {
    u64 r;
    asm("mov.b64 %0, {%1, %2};" : "=l"(r) : "f"(x), "f"(y));
    return r;
}
__device__ __forceinline__ float2 unpack2(u64 v) {
    float2 r;
    asm("mov.b64 {%0, %1}, %2;" : "=f"(r.x), "=f"(r.y) : "l"(v));
    return r;
}

// ---------------------------------------------------------------------------
__global__ void detect_ei(const void* ei, int Nn) {
    int lane = threadIdx.x & 31;
    long long v = ((const long long*)ei)[lane & 15];
    unsigned bad = __ballot_sync(0xffffffffu, v < 0 || v >= (long long)Nn);
    if (lane == 0 && blockIdx.x == 0) g_ei32 = bad ? 1 : 0;
}

__global__ void zero_small(int Nn) {
    int i = blockIdx.x * blockDim.x + threadIdx.x;
    int stride = gridDim.x * blockDim.x;
    for (int j = i; j < Nn; j += stride) g_cnt[j] = 0;
    if (i < 128) { g_bnsum[i] = 0.f; g_bnsq[i] = 0.f; }
}

__global__ void prep_weights(const float* __restrict__ w1l, const float* __restrict__ w1r,
                             const float* __restrict__ w2l, const float* __restrict__ w2r) {
    int t = blockIdx.x * blockDim.x + threadIdx.x;
    if (t < 256 * 128) {
        int k = t >> 7, c = t & 127;
        g_wT1[t] = (k < 128) ? w1l[c * 128 + k] : w1r[c * 128 + (k - 128)];
    }
    if (t < 256 * 48) {
        int k = t / 48, c = t - k * 48;
        float v = 0.f;
        if (c < 47) v = (k < 128) ? w2l[c * 128 + k] : w2r[c * 128 + (k - 128)];
        g_wT2[t] = v;
    }
}

__global__ void __launch_bounds__(256) build_adj(
    const void* __restrict__ ei, int E, int Nn)
{
    const int is32 = g_ei32;
    int t = blockIdx.x * blockDim.x + threadIdx.x;
    int stride = gridDim.x * blockDim.x;
    for (int e = t; e < E; e += stride) {
        int src, dst;
        if (is32) {
            src = ((const int*)ei)[e];
            dst = ((const int*)ei)[(size_t)E + e];
        } else {
            src = (int)((const long long*)ei)[e];
            dst = (int)((const long long*)ei)[(size_t)E + e];
        }
        if ((unsigned)src >= (unsigned)Nn || (unsigned)dst >= (unsigned)Nn) continue;
        int pos = atomicAdd(&g_cnt[dst], 1);
        if (pos < SLOTS) g_slot[(size_t)dst * SLOTS + pos] = src;
    }
}

// Gather-mean: one warp per node; lane l owns columns {l, l+32, l+64, l+96}.
// withBN: source is pre-BN h; apply relu(h*sc+sh) on the fly.
__global__ void __launch_bounds__(256) gather_mean(
    const float* __restrict__ feat, int withBN, int Nn)
{
    if (withBN) feat = (const float*)g_h;
    int gw   = (blockIdx.x * blockDim.x + threadIdx.x) >> 5;
    int lane = threadIdx.x & 31;
    int nw   = (gridDim.x * blockDim.x) >> 5;
    float sc0 = 1.f, sc1 = 1.f, sc2 = 1.f, sc3 = 1.f;
    float sh0 = 0.f, sh1 = 0.f, sh2 = 0.f, sh3 = 0.f;
    if (withBN) {
        sc0 = g_bnscale[lane];      sh0 = g_bnshift[lane];
        sc1 = g_bnscale[lane + 32]; sh1 = g_bnshift[lane + 32];
        sc2 = g_bnscale[lane + 64]; sh2 = g_bnshift[lane + 64];
        sc3 = g_bnscale[lane + 96]; sh3 = g_bnshift[lane + 96];
    }
    for (int n = gw; n < Nn; n += nw) {
        int cnt = g_cnt[n];
        int m = min(cnt, SLOTS);
        const int* sl = g_slot + (size_t)n * SLOTS;
        float a0 = 0.f, a1 = 0.f, a2 = 0.f, a3 = 0.f;
        if (withBN) {
            for (int j = 0; j < m; j++) {
                const float* p = feat + (size_t)sl[j] * 128 + lane;
                a0 += fmaxf(fmaf(p[0],  sc0, sh0), 0.f);
                a1 += fmaxf(fmaf(p[32], sc1, sh1), 0.f);
                a2 += fmaxf(fmaf(p[64], sc2, sh2), 0.f);
                a3 += fmaxf(fmaf(p[96], sc3, sh3), 0.f);
            }
        } else {
            int j = 0;
            for (; j + 2 <= m; j += 2) {
                int s0 = sl[j], s1 = sl[j + 1];
                const float* p0 = feat + (size_t)s0 * 128 + lane;
                const float* p1 = feat + (size_t)s1 * 128 + lane;
                a0 += p0[0] + p1[0];
                a1 += p0[32] + p1[32];
                a2 += p0[64] + p1[64];
                a3 += p0[96] + p1[96];
            }
            if (j < m) {
                const float* p0 = feat + (size_t)sl[j] * 128 + lane;
                a0 += p0[0]; a1 += p0[32]; a2 += p0[64]; a3 += p0[96];
            }
        }
        float r = 1.f / fmaxf((float)cnt, 1.f);
        float* dp = g_agg + (size_t)n * 128 + lane;
        dp[0]  = a0 * r;
        dp[32] = a1 * r;
        dp[64] = a2 * r;
        dp[96] = a3 * r;
    }
}

// ---------------------------------------------------------------------------
// GEMM1: h[n,c] = L2norm_row( [agg(n)|x(n)] @ wT1 + b1l ), c in [0,128)
// 128 threads, 64-node x 128-ch tile; per thread 4 nodes x 16 channels,
// FFMA2 mainloop; fused BN sum/sumsq. (R6 champion structure.)
// ---------------------------------------------------------------------------
__global__ void __launch_bounds__(128) sage_gemm1(
    const float* __restrict__ xin, const float* __restrict__ bias, int Nn)
{
    __shared__ float wS[KC * 128];        // 16 KB
    __shared__ float inS[64 * ASTR];      // 9.2 KB
    __shared__ float bnstage[2][4][128];  // 4 KB

    const int tid = threadIdx.x;
    const int ng = tid >> 3, cg = tid & 7;

    float2 bp[8];
#pragma unroll
    for (int p = 0; p < 8; p++) {
        int c = (p >> 1) * 32 + cg * 4 + (p & 1) * 2;
        bp[p] = *(const float2*)&bias[c];
    }

    float2 s1[8], s2[8];
#pragma unroll
    for (int p = 0; p < 8; p++) { s1[p] = make_float2(0.f, 0.f); s2[p] = make_float2(0.f, 0.f); }

    for (int base = blockIdx.x * 64; base < Nn; base += gridDim.x * 64) {
        int nrem = min(64, Nn - base);

        u64 acc[4][8];
#pragma unroll
        for (int i = 0; i < 4; i++)
#pragma unroll
            for (int p = 0; p < 8; p++) acc[i][p] = 0ull;

        for (int kc = 0; kc < 8; kc++) {
            __syncthreads();
            {
                const float4* wsrc = (const float4*)(g_wT1 + kc * KC * 128);
                float4* wdst = (float4*)wS;
                for (int i4 = tid; i4 < KC * 32; i4 += 128) wdst[i4] = wsrc[i4];
            }
            for (int i4 = tid; i4 < 64 * (KC / 4); i4 += 128) {
                int n = i4 >> 3;
                int kq = (i4 & 7) << 2;
                int k = kc * KC + kq;
                float4 v = make_float4(0.f, 0.f, 0.f, 0.f);
                if (n < nrem) {
                    if (k < 128) v = *(const float4*)&g_agg[(size_t)(base + n) * 128 + k];
                    else         v = *(const float4*)&xin[(size_t)(base + n) * 128 + (k - 128)];
                }
                *(float4*)&inS[n * ASTR + kq] = v;
            }
            __syncthreads();

#pragma unroll 4
            for (int kk = 0; kk < KC; kk++) {
                const ulonglong2* wrow = (const ulonglong2*)&wS[kk * 128];
                ulonglong2 w0 = wrow[cg];
                ulonglong2 w1 = wrow[cg + 8];
                ulonglong2 w2 = wrow[cg + 16];
                ulonglong2 w3 = wrow[cg + 24];
#pragma unroll
                for (int i = 0; i < 4; i++) {
                    float a = inS[(ng * 4 + i) * ASTR + kk];
                    u64 aa = pack2(a, a);
                    ffma2(acc[i][0], aa, w0.x);
                    ffma2(acc[i][1], aa, w0.y);
                    ffma2(acc[i][2], aa, w1.x);
                    ffma2(acc[i][3], aa, w1.y);
                    ffma2(acc[i][4], aa, w2.x);
                    ffma2(acc[i][5], aa, w2.y);
                    ffma2(acc[i][6], aa, w3.x);
                    ffma2(acc[i][7], aa, w3.y);
                }
            }
        }

        // Epilogue: bias, row L2 norm, store h (pre-BN), BN partials
#pragma unroll
        for (int i = 0; i < 4; i++) {
            float2 v[8];
            float ss = 0.f;
#pragma unroll
            for (int p = 0; p < 8; p++) {
                v[p] = unpack2(acc[i][p]);
                v[p].x += bp[p].x; v[p].y += bp[p].y;
                ss += v[p].x * v[p].x + v[p].y * v[p].y;
            }
            ss += __shfl_xor_sync(0xffffffffu, ss, 1);
            ss += __shfl_xor_sync(0xffffffffu, ss, 2);
            ss += __shfl_xor_sync(0xffffffffu, ss, 4);
            float inv = 1.f / fmaxf(sqrtf(ss), 1e-12f);
            int nl = ng * 4 + i;
            if (nl < nrem) {
                size_t n = (size_t)(base + nl);
#pragma unroll
                for (int m = 0; m < 4; m++) {
                    float2 r0 = v[2 * m], r1 = v[2 * m + 1];
                    float4 r;
                    r.x = r0.x * inv; r.y = r0.y * inv;
                    r.z = r1.x * inv; r.w = r1.y * inv;
                    *(float4*)&g_h[n * 128 + m * 32 + cg * 4] = r;
                    s1[2 * m].x += r.x;     s1[2 * m].y += r.y;
                    s1[2 * m + 1].x += r.z; s1[2 * m + 1].y += r.w;
                    s2[2 * m].x += r.x * r.x;     s2[2 * m].y += r.y * r.y;
                    s2[2 * m + 1].x += r.z * r.z; s2[2 * m + 1].y += r.w * r.w;
                }
            }
        }
        __syncthreads();
    }

    // BN partial reduction: shuffle over node-groups, stage via smem, 1 atomic/channel.
#pragma unroll
    for (int off = 8; off < 32; off <<= 1) {
#pragma unroll
        for (int p = 0; p < 8; p++) {
            s1[p].x += __shfl_xor_sync(0xffffffffu, s1[p].x, off);
            s1[p].y += __shfl_xor_sync(0xffffffffu, s1[p].y, off);
            s2[p].x += __shfl_xor_sync(0xffffffffu, s2[p].x, off);
            s2[p].y += __shfl_xor_sync(0xffffffffu, s2[p].y, off);
        }
    }
    int warp = tid >> 5, lane = tid & 31;
    if (lane < 8) {
#pragma unroll
        for (int p = 0; p < 8; p++) {
            int c = (p >> 1) * 32 + lane * 4 + (p & 1) * 2;
            bnstage[0][warp][c] = s1[p].x; bnstage[0][warp][c + 1] = s1[p].y;
            bnstage[1][warp][c] = s2[p].x; bnstage[1][warp][c + 1] = s2[p].y;
        }
    }
    __syncthreads();
    if (tid < 128) {
        float a0 = bnstage[0][0][tid] + bnstage[0][1][tid] + bnstage[0][2][tid] + bnstage[0][3][tid];
        float a1 = bnstage[1][0][tid] + bnstage[1][1][tid] + bnstage[1][2][tid] + bnstage[1][3][tid];
        atomicAdd(&g_bnsum[tid], a0);
        atomicAdd(&g_bnsq[tid], a1);
    }
}

__global__ void bn_finalize(const float* __restrict__ gamma, const float* __restrict__ beta, float invN) {
    int c = threadIdx.x;
    float mean = g_bnsum[c] * invN;
    float var = g_bnsq[c] * invN - mean * mean;
    float sc = gamma[c] * rsqrtf(var + 1e-5f);
    g_bnscale[c] = sc;
    g_bnshift[c] = beta[c] - mean * sc;
}

// ---------------------------------------------------------------------------
// GEMM2: out[n,c<47] = L2norm_row( [agg2 | relu(bn(h))] @ wT2 + b2l )
// 128 threads, 64-node tile (R6 structure); BN+ReLU fused into self-term staging.
// ---------------------------------------------------------------------------
__global__ void __launch_bounds__(128) sage_gemm2(
    const float* __restrict__ b2l, float* __restrict__ outp, int Nn)
{
    __shared__ float wS[KC * 48];       // 6 KB
    __shared__ float inS[64 * ASTR];    // 9.2 KB

    const int tid = threadIdx.x;
    const int ng = tid >> 3, cg = tid & 7;

    float2 b2[3];
#pragma unroll
    for (int m = 0; m < 3; m++) {
        int c = m * 16 + cg * 2;
        b2[m].x = (c < 47) ? b2l[c] : 0.f;
        b2[m].y = (c + 1 < 47) ? b2l[c + 1] : 0.f;
    }

    for (int base = blockIdx.x * 64; base < Nn; base += gridDim.x * 64) {
        int nrem = min(64, Nn - base);

        u64 acc[4][3];
#pragma unroll
        for (int i = 0; i < 4; i++)
#pragma unroll
            for (int m = 0; m < 3; m++) acc[i][m] = 0ull;

        for (int kc = 0; kc < 8; kc++) {
            __syncthreads();
            {
                const float4* wsrc = (const float4*)(g_wT2 + kc * KC * 48);
                float4* wdst = (float4*)wS;
                for (int i4 = tid; i4 < KC * 12; i4 += 128) wdst[i4] = wsrc[i4];
            }
            for (int i4 = tid; i4 < 64 * (KC / 4); i4 += 128) {
                int n = i4 >> 3;
                int kq = (i4 & 7) << 2;
                int k = kc * KC + kq;
                float4 v = make_float4(0.f, 0.f, 0.f, 0.f);
                if (n < nrem) {
                    if (k < 128) {
                        v = *(const float4*)&g_agg[(size_t)(base + n) * 128 + k];
                    } else {
                        int c = k - 128;
                        v = *(const float4*)&g_h[(size_t)(base + n) * 128 + c];
                        float4 sc = *(const float4*)&g_bnscale[c];
                        float4 sh = *(const float4*)&g_bnshift[c];
                        v.x = fmaxf(fmaf(v.x, sc.x, sh.x), 0.f);
                        v.y = fmaxf(fmaf(v.y, sc.y, sh.y), 0.f);
                        v.z = fmaxf(fmaf(v.z, sc.z, sh.z), 0.f);
                        v.w = fmaxf(fmaf(v.w, sc.w, sh.w), 0.f);
                    }
                }
                *(float4*)&inS[n * ASTR + kq] = v;
            }
            __syncthreads();

#pragma unroll 4
            for (int kk = 0; kk < KC; kk++) {
                u64 w0 = *(const u64*)&wS[kk * 48 +  0 + cg * 2];
                u64 w1 = *(const u64*)&wS[kk * 48 + 16 + cg * 2];
                u64 w2 = *(const u64*)&wS[kk * 48 + 32 + cg * 2];
#pragma unroll
                for (int i = 0; i < 4; i++) {
                    float a = inS[(ng * 4 + i) * ASTR + kk];
                    u64 aa = pack2(a, a);
                    ffma2(acc[i][0], aa, w0);
                    ffma2(acc[i][1], aa, w1);
                    ffma2(acc[i][2], aa, w2);
                }
            }
        }

#pragma unroll
        for (int i = 0; i < 4; i++) {
            float2 v[3];
            float ss = 0.f;
#pragma unroll
            for (int m = 0; m < 3; m++) {
                v[m] = unpack2(acc[i][m]);
                v[m].x += b2[m].x; v[m].y += b2[m].y;
                ss += v[m].x * v[m].x + v[m].y * v[m].y;
            }
            ss += __shfl_xor_sync(0xffffffffu, ss, 1);
            ss += __shfl_xor_sync(0xffffffffu, ss, 2);
            ss += __shfl_xor_sync(0xffffffffu, ss, 4);
            float inv = 1.f / fmaxf(sqrtf(ss), 1e-12f);
            int nl = ng * 4 + i;
            if (nl < nrem) {
                size_t n = (size_t)(base + nl);
#pragma unroll
                for (int m = 0; m < 3; m++) {
                    int c0 = m * 16 + cg * 2;
                    outp[n * 47 + c0] = v[m].x * inv;
                    if (c0 + 1 < 47) outp[n * 47 + c0 + 1] = v[m].y * inv;
                }
            }
        }
        __syncthreads();
    }
}

// ---------------------------------------------------------------------------
extern "C" void kernel_launch(void* const* d_in, const int* in_sizes, int n_in,
                              void* d_out, int out_size) {
    const float* x     = (const float*)d_in[0];
    const void*  ei    = d_in[1];
    const float* w1l   = (const float*)d_in[2];
    const float* b1l   = (const float*)d_in[3];
    const float* w1r   = (const float*)d_in[4];
    const float* gamma = (const float*)d_in[5];
    const float* beta  = (const float*)d_in[6];
    const float* w2l   = (const float*)d_in[7];
    const float* b2l   = (const float*)d_in[8];
    const float* w2r   = (const float*)d_in[9];
    int Nn = in_sizes[0] / 128;
    int E  = in_sizes[1] / 2;

    int gb = (Nn + 63) / 64;

    detect_ei<<<1, 32>>>(ei, Nn);
    zero_small<<<256, 256>>>(Nn);
    prep_weights<<<(256 * 128 + 255) / 256, 256>>>(w1l, w1r, w2l, w2r);
    build_adj<<<(E + 255) / 256, 256>>>(ei, E, Nn);
    gather_mean<<<2048, 256>>>(x, 0, Nn);
    sage_gemm1<<<gb, 128>>>(x, b1l, Nn);
    bn_finalize<<<1, 128>>>(gamma, beta, 1.0f / (float)Nn);
    gather_mean<<<2048, 256>>>(nullptr, 1, Nn);
    sage_gemm2<<<gb, 128>>>(b2l, (float*)d_out, Nn);
}

// round 9
// speedup vs baseline: 1.6083x; 1.2974x over previous
#include <cuda_runtime.h>
#include <cstdint>
#include <cstddef>

// ---------------------------------------------------------------------------
// GraphSAGE 2-layer (N=100000, E=800000, 128 -> 128 -> 47, fp32):
//   adjacency build -> gather-mean -> GEMM1(tf32 mma.sync, +bias+L2norm+BN)
//   -> BN finalize -> gather-mean(+BN+ReLU fused) -> GEMM2(tf32 mma.sync,
//   +BN self-term, +bias+L2norm) -> out
// Weights pre-interleaved [k>>2][c][k&3] + tf32-rounded for conflict-free
// B-fragment LDS. A staged in smem tf32-rounded at stride 36.
// ---------------------------------------------------------------------------

#define NMAX 100000
#define CH   128
#define KC   32          // K-chunk for GEMM staging
#define ASTR 36          // inS row stride
#define SLOTS 64

typedef unsigned long long u64;
typedef unsigned int u32;

__device__ __align__(16) float g_agg[(size_t)NMAX * CH];
__device__ __align__(16) float g_h[(size_t)NMAX * CH];
__device__ __align__(16) int   g_cnt[NMAX];
__device__ __align__(16) int   g_slot[(size_t)NMAX * SLOTS];
__device__ __align__(16) float g_wT1[256 * 128];   // interleaved [k>>2][c][k&3], tf32
__device__ __align__(16) float g_wT2[256 * 48];    // interleaved [k>>2][c48][k&3], tf32
__device__ __align__(16) float g_bnsum[128];
__device__ __align__(16) float g_bnsq[128];
__device__ __align__(16) float g_bnscale[128];
__device__ __align__(16) float g_bnshift[128];
__device__ int g_ei32;

// ---- helpers ---------------------------------------------------------------
__device__ __forceinline__ float tf32r(float x) {
    u32 u;
    asm("cvt.rna.tf32.f32 %0, %1;" : "=r"(u) : "f"(x));
    return __uint_as_float(u);
}

__device__ __forceinline__ void mma_tf32(float* c, const u32* a, u32 b0, u32 b1) {
    asm volatile(
        "mma.sync.aligned.m16n8k8.row.col.f32.tf32.tf32.f32 "
        "{%0,%1,%2,%3}, {%4,%5,%6,%7}, {%8,%9}, {%0,%1,%2,%3};"
        : "+f"(c[0]), "+f"(c[1]), "+f"(c[2]), "+f"(c[3])
        : "r"(a[0]), "r"(a[1]), "r"(a[2]), "r"(a[3]), "r"(b0), "r"(b1));
}

// ---------------------------------------------------------------------------
__global__ void detect_ei(const void* ei, int Nn) {
    int lane = threadIdx.x & 31;
    long long v = ((const long long*)ei)[lane & 15];
    unsigned bad = __ballot_sync(0xffffffffu, v < 0 || v >= (long long)Nn);
    if (lane == 0 && blockIdx.x == 0) g_ei32 = bad ? 1 : 0;
}

__global__ void zero_small(int Nn) {
    int i = blockIdx.x * blockDim.x + threadIdx.x;
    int stride = gridDim.x * blockDim.x;
    for (int j = i; j < Nn; j += stride) g_cnt[j] = 0;
    if (i < 128) { g_bnsum[i] = 0.f; g_bnsq[i] = 0.f; }
}

// Interleave + tf32-round weights: dest[(k>>2)*(C*4) + c*4 + (k&3)].
__global__ void prep_weights(const float* __restrict__ w1l, const float* __restrict__ w1r,
                             const float* __restrict__ w2l, const float* __restrict__ w2r) {
    int t = blockIdx.x * blockDim.x + threadIdx.x;
    if (t < 256 * 128) {
        int k = t >> 7, c = t & 127;
        float v = (k < 128) ? w1l[c * 128 + k] : w1r[c * 128 + (k - 128)];
        g_wT1[(k >> 2) * 512 + c * 4 + (k & 3)] = tf32r(v);
    }
    if (t < 256 * 48) {
        int k = t / 48, c = t - k * 48;
        float v = 0.f;
        if (c < 47) v = (k < 128) ? w2l[c * 128 + k] : w2r[c * 128 + (k - 128)];
        g_wT2[(k >> 2) * 192 + c * 4 + (k & 3)] = tf32r(v);
    }
}

__global__ void __launch_bounds__(256) build_adj(
    const void* __restrict__ ei, int E, int Nn)
{
    const int is32 = g_ei32;
    int t = blockIdx.x * blockDim.x + threadIdx.x;
    int stride = gridDim.x * blockDim.x;
    for (int e = t; e < E; e += stride) {
        int src, dst;
        if (is32) {
            src = ((const int*)ei)[e];
            dst = ((const int*)ei)[(size_t)E + e];
        } else {
            src = (int)((const long long*)ei)[e];
            dst = (int)((const long long*)ei)[(size_t)E + e];
        }
        if ((unsigned)src >= (unsigned)Nn || (unsigned)dst >= (unsigned)Nn) continue;
        int pos = atomicAdd(&g_cnt[dst], 1);
        if (pos < SLOTS) g_slot[(size_t)dst * SLOTS + pos] = src;
    }
}

// Gather-mean: one warp per node; lane l owns columns {l, l+32, l+64, l+96}.
__global__ void __launch_bounds__(256) gather_mean(
    const float* __restrict__ feat, int withBN, int Nn)
{
    if (withBN) feat = (const float*)g_h;
    int gw   = (blockIdx.x * blockDim.x + threadIdx.x) >> 5;
    int lane = threadIdx.x & 31;
    int nw   = (gridDim.x * blockDim.x) >> 5;
    float sc0 = 1.f, sc1 = 1.f, sc2 = 1.f, sc3 = 1.f;
    float sh0 = 0.f, sh1 = 0.f, sh2 = 0.f, sh3 = 0.f;
    if (withBN) {
        sc0 = g_bnscale[lane];      sh0 = g_bnshift[lane];
        sc1 = g_bnscale[lane + 32]; sh1 = g_bnshift[lane + 32];
        sc2 = g_bnscale[lane + 64]; sh2 = g_bnshift[lane + 64];
        sc3 = g_bnscale[lane + 96]; sh3 = g_bnshift[lane + 96];
    }
    for (int n = gw; n < Nn; n += nw) {
        int cnt = g_cnt[n];
        int m = min(cnt, SLOTS);
        const int* sl = g_slot + (size_t)n * SLOTS;
        float a0 = 0.f, a1 = 0.f, a2 = 0.f, a3 = 0.f;
        if (withBN) {
            for (int j = 0; j < m; j++) {
                const float* p = feat + (size_t)sl[j] * 128 + lane;
                a0 += fmaxf(fmaf(p[0],  sc0, sh0), 0.f);
                a1 += fmaxf(fmaf(p[32], sc1, sh1), 0.f);
                a2 += fmaxf(fmaf(p[64], sc2, sh2), 0.f);
                a3 += fmaxf(fmaf(p[96], sc3, sh3), 0.f);
            }
        } else {
            int j = 0;
            for (; j + 2 <= m; j += 2) {
                int s0 = sl[j], s1 = sl[j + 1];
                const float* p0 = feat + (size_t)s0 * 128 + lane;
                const float* p1 = feat + (size_t)s1 * 128 + lane;
                a0 += p0[0] + p1[0];
                a1 += p0[32] + p1[32];
                a2 += p0[64] + p1[64];
                a3 += p0[96] + p1[96];
            }
            if (j < m) {
                const float* p0 = feat + (size_t)sl[j] * 128 + lane;
                a0 += p0[0]; a1 += p0[32]; a2 += p0[64]; a3 += p0[96];
            }
        }
        float r = 1.f / fmaxf((float)cnt, 1.f);
        float* dp = g_agg + (size_t)n * 128 + lane;
        dp[0]  = a0 * r;
        dp[32] = a1 * r;
        dp[64] = a2 * r;
        dp[96] = a3 * r;
    }
}

// ---------------------------------------------------------------------------
// GEMM1 (tf32 mma): h[n,c] = L2norm_row([agg|x] @ W1 + b1l), c in [0,128)
// 4 warps as 2x2 (wm,wn); warp = rows wm*32..+32 (2 m-blocks), cols wn*64..+64
// (8 n-blocks). Fused BN sum/sumsq over stored h.
// ---------------------------------------------------------------------------
__global__ void __launch_bounds__(128) sage_gemm1(
    const float* __restrict__ xin, const float* __restrict__ bias, int Nn)
{
    __shared__ float wS[KC * 128];        // 16 KB, interleaved chunk
    __shared__ float inS[64 * ASTR];      // 9 KB, tf32-rounded
    __shared__ float ssS[2][64];
    __shared__ float bnstage[2][4][128];  // 4 KB

    const int tid  = threadIdx.x;
    const int warp = tid >> 5, lane = tid & 31;
    const int wm = warp >> 1, wn = warp & 1;
    const int qr = lane >> 2, qk = lane & 3;

    float2 bp[8];
#pragma unroll
    for (int nb = 0; nb < 8; nb++)
        bp[nb] = *(const float2*)&bias[wn * 64 + nb * 8 + 2 * qk];

    float2 s1[8], s2[8];
#pragma unroll
    for (int nb = 0; nb < 8; nb++) { s1[nb] = make_float2(0.f, 0.f); s2[nb] = make_float2(0.f, 0.f); }

    for (int base = blockIdx.x * 64; base < Nn; base += gridDim.x * 64) {
        int nrem = min(64, Nn - base);

        float acc[2][8][4];
#pragma unroll
        for (int mb = 0; mb < 2; mb++)
#pragma unroll
            for (int nb = 0; nb < 8; nb++)
#pragma unroll
                for (int q = 0; q < 4; q++) acc[mb][nb][q] = 0.f;

        for (int kc = 0; kc < 8; kc++) {
            __syncthreads();
            {   // weights chunk: contiguous 4096 floats (interleaved layout)
                const float4* wsrc = (const float4*)(g_wT1 + kc * 4096);
                float4* wdst = (float4*)wS;
                for (int i4 = tid; i4 < 1024; i4 += 128) wdst[i4] = wsrc[i4];
            }
            // inputs: 64 nodes x 32 k, tf32-rounded
            for (int i4 = tid; i4 < 512; i4 += 128) {
                int n = i4 >> 3;
                int kq = (i4 & 7) << 2;
                int k = kc * KC + kq;
                float4 v = make_float4(0.f, 0.f, 0.f, 0.f);
                if (n < nrem) {
                    if (k < 128) v = *(const float4*)&g_agg[(size_t)(base + n) * 128 + k];
                    else         v = *(const float4*)&xin[(size_t)(base + n) * 128 + (k - 128)];
                }
                v.x = tf32r(v.x); v.y = tf32r(v.y); v.z = tf32r(v.z); v.w = tf32r(v.w);
                *(float4*)&inS[n * ASTR + kq] = v;
            }
            __syncthreads();

#pragma unroll
            for (int ks = 0; ks < 4; ks++) {
                int kb = ks * 8;
                u32 b0[8], b1[8];
                int wbase = (kb >> 2) * 512 + wn * 256 + qr * 4 + qk;
#pragma unroll
                for (int nb = 0; nb < 8; nb++) {
                    b0[nb] = __float_as_uint(wS[wbase + nb * 32]);
                    b1[nb] = __float_as_uint(wS[wbase + 512 + nb * 32]);
                }
                u32 a[2][4];
#pragma unroll
                for (int mb = 0; mb < 2; mb++) {
                    int r0 = (wm * 32 + mb * 16 + qr) * ASTR + kb + qk;
                    a[mb][0] = __float_as_uint(inS[r0]);
                    a[mb][1] = __float_as_uint(inS[r0 + 8 * ASTR]);
                    a[mb][2] = __float_as_uint(inS[r0 + 4]);
                    a[mb][3] = __float_as_uint(inS[r0 + 8 * ASTR + 4]);
                }
#pragma unroll
                for (int mb = 0; mb < 2; mb++)
#pragma unroll
                    for (int nb = 0; nb < 8; nb++)
                        mma_tf32(acc[mb][nb], a[mb], b0[nb], b1[nb]);
            }
        }

        // Epilogue: bias, row L2 norm (quad shuffle + cross-half smem), store, BN
        float ssp[2][2] = {{0.f, 0.f}, {0.f, 0.f}};
#pragma unroll
        for (int mb = 0; mb < 2; mb++)
#pragma unroll
            for (int nb = 0; nb < 8; nb++) {
                acc[mb][nb][0] += bp[nb].x; acc[mb][nb][1] += bp[nb].y;
                acc[mb][nb][2] += bp[nb].x; acc[mb][nb][3] += bp[nb].y;
                ssp[mb][0] += acc[mb][nb][0] * acc[mb][nb][0] + acc[mb][nb][1] * acc[mb][nb][1];
                ssp[mb][1] += acc[mb][nb][2] * acc[mb][nb][2] + acc[mb][nb][3] * acc[mb][nb][3];
            }
#pragma unroll
        for (int mb = 0; mb < 2; mb++)
#pragma unroll
            for (int rs = 0; rs < 2; rs++) {
                ssp[mb][rs] += __shfl_xor_sync(0xffffffffu, ssp[mb][rs], 1);
                ssp[mb][rs] += __shfl_xor_sync(0xffffffffu, ssp[mb][rs], 2);
            }
        if (qk == 0) {
#pragma unroll
            for (int mb = 0; mb < 2; mb++)
#pragma unroll
                for (int rs = 0; rs < 2; rs++)
                    ssS[wn][wm * 32 + mb * 16 + rs * 8 + qr] = ssp[mb][rs];
        }
        __syncthreads();
        float inv[2][2];
#pragma unroll
        for (int mb = 0; mb < 2; mb++)
#pragma unroll
            for (int rs = 0; rs < 2; rs++) {
                int lr = wm * 32 + mb * 16 + rs * 8 + qr;
                float tot = ssS[0][lr] + ssS[1][lr];
                inv[mb][rs] = 1.f / fmaxf(sqrtf(tot), 1e-12f);
            }
#pragma unroll
        for (int mb = 0; mb < 2; mb++) {
            int lr0 = wm * 32 + mb * 16 + qr;
            int lr1 = lr0 + 8;
#pragma unroll
            for (int nb = 0; nb < 8; nb++) {
                int col = wn * 64 + nb * 8 + 2 * qk;
                if (lr0 < nrem) {
                    float vx = acc[mb][nb][0] * inv[mb][0];
                    float vy = acc[mb][nb][1] * inv[mb][0];
                    *(float2*)&g_h[(size_t)(base + lr0) * 128 + col] = make_float2(vx, vy);
                    s1[nb].x += vx; s1[nb].y += vy;
                    s2[nb].x += vx * vx; s2[nb].y += vy * vy;
                }
                if (lr1 < nrem) {
                    float vx = acc[mb][nb][2] * inv[mb][1];
                    float vy = acc[mb][nb][3] * inv[mb][1];
                    *(float2*)&g_h[(size_t)(base + lr1) * 128 + col] = make_float2(vx, vy);
                    s1[nb].x += vx; s1[nb].y += vy;
                    s2[nb].x += vx * vx; s2[nb].y += vy * vy;
                }
            }
        }
        __syncthreads();
    }

    // BN reduction: sum over the 8 lanes sharing qk (rows), stage per warp, combine.
#pragma unroll
    for (int off = 4; off < 32; off <<= 1) {
#pragma unroll
        for (int nb = 0; nb < 8; nb++) {
            s1[nb].x += __shfl_xor_sync(0xffffffffu, s1[nb].x, off);
            s1[nb].y += __shfl_xor_sync(0xffffffffu, s1[nb].y, off);
            s2[nb].x += __shfl_xor_sync(0xffffffffu, s2[nb].x, off);
            s2[nb].y += __shfl_xor_sync(0xffffffffu, s2[nb].y, off);
        }
    }
    if (lane < 4) {
#pragma unroll
        for (int nb = 0; nb < 8; nb++) {
            int c = wn * 64 + nb * 8 + 2 * lane;
            bnstage[0][warp][c] = s1[nb].x; bnstage[0][warp][c + 1] = s1[nb].y;
            bnstage[1][warp][c] = s2[nb].x; bnstage[1][warp][c + 1] = s2[nb].y;
        }
    }
    __syncthreads();
    if (tid < 128) {
        int wsel = tid >> 6;  // which wn owns this channel
        float a0 = bnstage[0][wsel][tid] + bnstage[0][2 + wsel][tid];
        float a1 = bnstage[1][wsel][tid] + bnstage[1][2 + wsel][tid];
        atomicAdd(&g_bnsum[tid], a0);
        atomicAdd(&g_bnsq[tid], a1);
    }
}

__global__ void bn_finalize(const float* __restrict__ gamma, const float* __restrict__ beta, float invN) {
    int c = threadIdx.x;
    float mean = g_bnsum[c] * invN;
    float var = g_bnsq[c] * invN - mean * mean;
    float sc = gamma[c] * rsqrtf(var + 1e-5f);
    g_bnscale[c] = sc;
    g_bnshift[c] = beta[c] - mean * sc;
}

// ---------------------------------------------------------------------------
// GEMM2 (tf32 mma): out[n,c<47] = L2norm_row([agg2 | relu(bn(h))] @ W2 + b2l)
// Warp (wm,wn): rows wm*32 (2 m-blocks), cols wn*24 (3 n-blocks, 48 padded).
// ---------------------------------------------------------------------------
__global__ void __launch_bounds__(128) sage_gemm2(
    const float* __restrict__ b2l, float* __restrict__ outp, int Nn)
{
    __shared__ float wS[KC * 48];       // 6 KB interleaved chunk
    __shared__ float inS[64 * ASTR];    // 9 KB
    __shared__ float ssS[2][64];

    const int tid  = threadIdx.x;
    const int warp = tid >> 5, lane = tid & 31;
    const int wm = warp >> 1, wn = warp & 1;
    const int qr = lane >> 2, qk = lane & 3;

    float2 bp[3];
#pragma unroll
    for (int nb = 0; nb < 3; nb++) {
        int c = wn * 24 + nb * 8 + 2 * qk;
        bp[nb].x = (c < 47) ? b2l[c] : 0.f;
        bp[nb].y = (c + 1 < 47) ? b2l[c + 1] : 0.f;
    }

    for (int base = blockIdx.x * 64; base < Nn; base += gridDim.x * 64) {
        int nrem = min(64, Nn - base);

        float acc[2][3][4];
#pragma unroll
        for (int mb = 0; mb < 2; mb++)
#pragma unroll
            for (int nb = 0; nb < 3; nb++)
#pragma unroll
                for (int q = 0; q < 4; q++) acc[mb][nb][q] = 0.f;

        for (int kc = 0; kc < 8; kc++) {
            __syncthreads();
            {
                const float4* wsrc = (const float4*)(g_wT2 + kc * 1536);
                float4* wdst = (float4*)wS;
                for (int i4 = tid; i4 < 384; i4 += 128) wdst[i4] = wsrc[i4];
            }
            for (int i4 = tid; i4 < 512; i4 += 128) {
                int n = i4 >> 3;
                int kq = (i4 & 7) << 2;
                int k = kc * KC + kq;
                float4 v = make_float4(0.f, 0.f, 0.f, 0.f);
                if (n < nrem) {
                    if (k < 128) {
                        v = *(const float4*)&g_agg[(size_t)(base + n) * 128 + k];
                    } else {
                        int c = k - 128;
                        v = *(const float4*)&g_h[(size_t)(base + n) * 128 + c];
                        float4 sc = *(const float4*)&g_bnscale[c];
                        float4 sh = *(const float4*)&g_bnshift[c];
                        v.x = fmaxf(fmaf(v.x, sc.x, sh.x), 0.f);
                        v.y = fmaxf(fmaf(v.y, sc.y, sh.y), 0.f);
                        v.z = fmaxf(fmaf(v.z, sc.z, sh.z), 0.f);
                        v.w = fmaxf(fmaf(v.w, sc.w, sh.w), 0.f);
                    }
                }
                v.x = tf32r(v.x); v.y = tf32r(v.y); v.z = tf32r(v.z); v.w = tf32r(v.w);
                *(float4*)&inS[n * ASTR + kq] = v;
            }
            __syncthreads();

#pragma unroll
            for (int ks = 0; ks < 4; ks++) {
                int kb = ks * 8;
                u32 b0[3], b1[3];
                int wbase = (kb >> 2) * 192 + wn * 96 + qr * 4 + qk;
#pragma unroll
                for (int nb = 0; nb < 3; nb++) {
                    b0[nb] = __float_as_uint(wS[wbase + nb * 32]);
                    b1[nb] = __float_as_uint(wS[wbase + 192 + nb * 32]);
                }
                u32 a[2][4];
#pragma unroll
                for (int mb = 0; mb < 2; mb++) {
                    int r0 = (wm * 32 + mb * 16 + qr) * ASTR + kb + qk;
                    a[mb][0] = __float_as_uint(inS[r0]);
                    a[mb][1] = __float_as_uint(inS[r0 + 8 * ASTR]);
                    a[mb][2] = __float_as_uint(inS[r0 + 4]);
                    a[mb][3] = __float_as_uint(inS[r0 + 8 * ASTR + 4]);
                }
#pragma unroll
                for (int mb = 0; mb < 2; mb++)
#pragma unroll
                    for (int nb = 0; nb < 3; nb++)
                        mma_tf32(acc[mb][nb], a[mb], b0[nb], b1[nb]);
            }
        }

        // Epilogue: bias, row L2 norm over 47 cols (pad col is 0), store
        float ssp[2][2] = {{0.f, 0.f}, {0.f, 0.f}};
#pragma unroll
        for (int mb = 0; mb < 2; mb++)
#pragma unroll
            for (int nb = 0; nb < 3; nb++) {
                acc[mb][nb][0] += bp[nb].x; acc[mb][nb][1] += bp[nb].y;
                acc[mb][nb][2] += bp[nb].x; acc[mb][nb][3] += bp[nb].y;
                ssp[mb][0] += acc[mb][nb][0] * acc[mb][nb][0] + acc[mb][nb][1] * acc[mb][nb][1];
                ssp[mb][1] += acc[mb][nb][2] * acc[mb][nb][2] + acc[mb][nb][3] * acc[mb][nb][3];
            }
#pragma unroll
        for (int mb = 0; mb < 2; mb++)
#pragma unroll
            for (int rs = 0; rs < 2; rs++) {
                ssp[mb][rs] += __shfl_xor_sync(0xffffffffu, ssp[mb][rs], 1);
                ssp[mb][rs] += __shfl_xor_sync(0xffffffffu, ssp[mb][rs], 2);
            }
        if (qk == 0) {
#pragma unroll
            for (int mb = 0; mb < 2; mb++)
#pragma unroll
                for (int rs = 0; rs < 2; rs++)
                    ssS[wn][wm * 32 + mb * 16 + rs * 8 + qr] = ssp[mb][rs];
        }
        __syncthreads();
        float inv[2][2];
#pragma unroll
        for (int mb = 0; mb < 2; mb++)
#pragma unroll
            for (int rs = 0; rs < 2; rs++) {
                int lr = wm * 32 + mb * 16 + rs * 8 + qr;
                float tot = ssS[0][lr] + ssS[1][lr];
                inv[mb][rs] = 1.f / fmaxf(sqrtf(tot), 1e-12f);
            }
#pragma unroll
        for (int mb = 0; mb < 2; mb++) {
            int lr0 = wm * 32 + mb * 16 + qr;
            int lr1 = lr0 + 8;
#pragma unroll
            for (int nb = 0; nb < 3; nb++) {
                int c0 = wn * 24 + nb * 8 + 2 * qk;
                if (lr0 < nrem) {
                    size_t o = (size_t)(base + lr0) * 47;
                    if (c0 < 47)     outp[o + c0]     = acc[mb][nb][0] * inv[mb][0];
                    if (c0 + 1 < 47) outp[o + c0 + 1] = acc[mb][nb][1] * inv[mb][0];
                }
                if (lr1 < nrem) {
                    size_t o = (size_t)(base + lr1) * 47;
                    if (c0 < 47)     outp[o + c0]     = acc[mb][nb][2] * inv[mb][1];
                    if (c0 + 1 < 47) outp[o + c0 + 1] = acc[mb][nb][3] * inv[mb][1];
                }
            }
        }
        __syncthreads();
    }
}

// ---------------------------------------------------------------------------
extern "C" void kernel_launch(void* const* d_in, const int* in_sizes, int n_in,
                              void* d_out, int out_size) {
    const float* x     = (const float*)d_in[0];
    const void*  ei    = d_in[1];
    const float* w1l   = (const float*)d_in[2];
    const float* b1l   = (const float*)d_in[3];
    const float* w1r   = (const float*)d_in[4];
    const float* gamma = (const float*)d_in[5];
    const float* beta  = (const float*)d_in[6];
    const float* w2l   = (const float*)d_in[7];
    const float* b2l   = (const float*)d_in[8];
    const float* w2r   = (const float*)d_in[9];
    int Nn = in_sizes[0] / 128;
    int E  = in_sizes[1] / 2;

    int gb = (Nn + 63) / 64;

    detect_ei<<<1, 32>>>(ei, Nn);
    zero_small<<<256, 256>>>(Nn);
    prep_weights<<<(256 * 128 + 255) / 256, 256>>>(w1l, w1r, w2l, w2r);
    build_adj<<<(E + 255) / 256, 256>>>(ei, E, Nn);
    gather_mean<<<2048, 256>>>(x, 0, Nn);
    sage_gemm1<<<gb, 128>>>(x, b1l, Nn);
    bn_finalize<<<1, 128>>>(gamma, beta, 1.0f / (float)Nn);
    gather_mean<<<2048, 256>>>(nullptr, 1, Nn);
    sage_gemm2<<<gb, 128>>>(b2l, (float*)d_out, Nn);
}

// round 10
// speedup vs baseline: 2.1052x; 1.3090x over previous
#include <cuda_runtime.h>
#include <cstdint>
#include <cstddef>

// ---------------------------------------------------------------------------
// GraphSAGE 2-layer (N=100000, E=800000, 128 -> 128 -> 47, fp32):
//   adjacency build -> gather-mean(float4, tf32-rounded out) ->
//   GEMM1(tf32 mma.sync, cp.async staging, +bias+L2norm+BN) -> BN finalize ->
//   gather-mean(+BN+ReLU fused) -> GEMM2(tf32 mma.sync, +BN self-term) -> out
// ---------------------------------------------------------------------------

#define NMAX 100000
#define CH   128
#define KC   32
#define ASTR 36
#define SLOTS 64

typedef unsigned long long u64;
typedef unsigned int u32;

__device__ __align__(16) float g_agg[(size_t)NMAX * CH];   // tf32-rounded
__device__ __align__(16) float g_h[(size_t)NMAX * CH];
__device__ __align__(16) int   g_cnt[NMAX];
__device__ __align__(16) int   g_slot[(size_t)NMAX * SLOTS];
__device__ __align__(16) float g_wT1[256 * 128];   // interleaved [k>>2][c][k&3], tf32
__device__ __align__(16) float g_wT2[256 * 48];    // interleaved [k>>2][c48][k&3], tf32
__device__ __align__(16) float g_bnsum[128];
__device__ __align__(16) float g_bnsq[128];
__device__ __align__(16) float g_bnscale[128];
__device__ __align__(16) float g_bnshift[128];
__device__ int g_ei32;

// ---- helpers ---------------------------------------------------------------
__device__ __forceinline__ float tf32r(float x) {
    u32 u;
    asm("cvt.rna.tf32.f32 %0, %1;" : "=r"(u) : "f"(x));
    return __uint_as_float(u);
}

__device__ __forceinline__ void mma_tf32(float* c, const u32* a, u32 b0, u32 b1) {
    asm volatile(
        "mma.sync.aligned.m16n8k8.row.col.f32.tf32.tf32.f32 "
        "{%0,%1,%2,%3}, {%4,%5,%6,%7}, {%8,%9}, {%0,%1,%2,%3};"
        : "+f"(c[0]), "+f"(c[1]), "+f"(c[2]), "+f"(c[3])
        : "r"(a[0]), "r"(a[1]), "r"(a[2]), "r"(a[3]), "r"(b0), "r"(b1));
}

__device__ __forceinline__ void cpa16(void* smem, const void* g) {
    u32 s = (u32)__cvta_generic_to_shared(smem);
    asm volatile("cp.async.cg.shared.global [%0], [%1], 16;" :: "r"(s), "l"(g));
}
__device__ __forceinline__ void cpa16_zero(void* smem, const void* g) {
    u32 s = (u32)__cvta_generic_to_shared(smem);
    asm volatile("cp.async.cg.shared.global [%0], [%1], 16, %2;"
                 :: "r"(s), "l"(g), "r"(0u));
}
__device__ __forceinline__ void cpa_commit_wait() {
    asm volatile("cp.async.commit_group;" ::: "memory");
    asm volatile("cp.async.wait_group 0;" ::: "memory");
}

__device__ __forceinline__ float4 bnrelu4(float4 v, float4 sc, float4 sh) {
    v.x = fmaxf(fmaf(v.x, sc.x, sh.x), 0.f);
    v.y = fmaxf(fmaf(v.y, sc.y, sh.y), 0.f);
    v.z = fmaxf(fmaf(v.z, sc.z, sh.z), 0.f);
    v.w = fmaxf(fmaf(v.w, sc.w, sh.w), 0.f);
    return v;
}

// ---------------------------------------------------------------------------
__global__ void detect_ei(const void* ei, int Nn) {
    int lane = threadIdx.x & 31;
    long long v = ((const long long*)ei)[lane & 15];
    unsigned bad = __ballot_sync(0xffffffffu, v < 0 || v >= (long long)Nn);
    if (lane == 0 && blockIdx.x == 0) g_ei32 = bad ? 1 : 0;
}

// Interleave + tf32-round weights; also zero cnt / BN accumulators.
__global__ void prep_weights(const float* __restrict__ w1l, const float* __restrict__ w1r,
                             const float* __restrict__ w2l, const float* __restrict__ w2r,
                             int Nn) {
    int t = blockIdx.x * blockDim.x + threadIdx.x;
    int stride = gridDim.x * blockDim.x;
    if (t < 256 * 128) {
        int k = t >> 7, c = t & 127;
        float v = (k < 128) ? w1l[c * 128 + k] : w1r[c * 128 + (k - 128)];
        g_wT1[(k >> 2) * 512 + c * 4 + (k & 3)] = tf32r(v);
    }
    if (t < 256 * 48) {
        int k = t / 48, c = t - k * 48;
        float v = 0.f;
        if (c < 47) v = (k < 128) ? w2l[c * 128 + k] : w2r[c * 128 + (k - 128)];
        g_wT2[(k >> 2) * 192 + c * 4 + (k & 3)] = tf32r(v);
    }
    for (int j = t; j < Nn; j += stride) g_cnt[j] = 0;
    if (t < 128) { g_bnsum[t] = 0.f; g_bnsq[t] = 0.f; }
}

__global__ void __launch_bounds__(256) build_adj(
    const void* __restrict__ ei, int E, int Nn)
{
    const int is32 = g_ei32;
    int t = blockIdx.x * blockDim.x + threadIdx.x;
    int stride = gridDim.x * blockDim.x;
    for (int e = t; e < E; e += stride) {
        int src, dst;
        if (is32) {
            src = ((const int*)ei)[e];
            dst = ((const int*)ei)[(size_t)E + e];
        } else {
            src = (int)((const long long*)ei)[e];
            dst = (int)((const long long*)ei)[(size_t)E + e];
        }
        if ((unsigned)src >= (unsigned)Nn || (unsigned)dst >= (unsigned)Nn) continue;
        int pos = atomicAdd(&g_cnt[dst], 1);
        if (pos < SLOTS) g_slot[(size_t)dst * SLOTS + pos] = src;
    }
}

// Gather-mean: one warp per node; lane owns channels 4l..4l+3 (float4).
// Output is tf32-rounded (consumed only by tf32 GEMMs).
__global__ void __launch_bounds__(256) gather_mean(
    const float* __restrict__ feat, int withBN, int Nn)
{
    if (withBN) feat = (const float*)g_h;
    int gw   = (blockIdx.x * blockDim.x + threadIdx.x) >> 5;
    int lane = threadIdx.x & 31;
    int nw   = (gridDim.x * blockDim.x) >> 5;
    float4 sc = make_float4(1.f, 1.f, 1.f, 1.f);
    float4 sh = make_float4(0.f, 0.f, 0.f, 0.f);
    if (withBN) {
        sc = ((const float4*)g_bnscale)[lane];
        sh = ((const float4*)g_bnshift)[lane];
    }
    for (int n = gw; n < Nn; n += nw) {
        int cnt = g_cnt[n];
        int m = min(cnt, SLOTS);
        const int* sl = g_slot + (size_t)n * SLOTS;
        float4 a = make_float4(0.f, 0.f, 0.f, 0.f);
        int j = 0;
        for (; j + 4 <= m; j += 4) {
            int s0 = sl[j], s1 = sl[j + 1], s2 = sl[j + 2], s3 = sl[j + 3];
            float4 v0 = ((const float4*)(feat + (size_t)s0 * 128))[lane];
            float4 v1 = ((const float4*)(feat + (size_t)s1 * 128))[lane];
            float4 v2 = ((const float4*)(feat + (size_t)s2 * 128))[lane];
            float4 v3 = ((const float4*)(feat + (size_t)s3 * 128))[lane];
            if (withBN) {
                v0 = bnrelu4(v0, sc, sh); v1 = bnrelu4(v1, sc, sh);
                v2 = bnrelu4(v2, sc, sh); v3 = bnrelu4(v3, sc, sh);
            }
            a.x += (v0.x + v1.x) + (v2.x + v3.x);
            a.y += (v0.y + v1.y) + (v2.y + v3.y);
            a.z += (v0.z + v1.z) + (v2.z + v3.z);
            a.w += (v0.w + v1.w) + (v2.w + v3.w);
        }
        for (; j < m; j++) {
            float4 v = ((const float4*)(feat + (size_t)sl[j] * 128))[lane];
            if (withBN) v = bnrelu4(v, sc, sh);
            a.x += v.x; a.y += v.y; a.z += v.z; a.w += v.w;
        }
        float r = 1.f / fmaxf((float)cnt, 1.f);
        a.x = tf32r(a.x * r); a.y = tf32r(a.y * r);
        a.z = tf32r(a.z * r); a.w = tf32r(a.w * r);
        ((float4*)(g_agg + (size_t)n * 128))[lane] = a;
    }
}

// ---------------------------------------------------------------------------
// GEMM1 (tf32 mma): h[n,c] = L2norm_row([agg|x] @ W1 + b1l)
// Staging: weights + agg-half via cp.async (pre-rounded), x-half via LDG+cvt.
// ---------------------------------------------------------------------------
__global__ void __launch_bounds__(128) sage_gemm1(
    const float* __restrict__ xin, const float* __restrict__ bias, int Nn)
{
    __shared__ float wS[KC * 128];
    __shared__ float inS[64 * ASTR];
    __shared__ float ssS[2][64];
    __shared__ float bnstage[2][4][128];

    const int tid  = threadIdx.x;
    const int warp = tid >> 5, lane = tid & 31;
    const int wm = warp >> 1, wn = warp & 1;
    const int qr = lane >> 2, qk = lane & 3;

    float2 bp[8];
#pragma unroll
    for (int nb = 0; nb < 8; nb++)
        bp[nb] = *(const float2*)&bias[wn * 64 + nb * 8 + 2 * qk];

    float2 s1[8], s2[8];
#pragma unroll
    for (int nb = 0; nb < 8; nb++) { s1[nb] = make_float2(0.f, 0.f); s2[nb] = make_float2(0.f, 0.f); }

    for (int base = blockIdx.x * 64; base < Nn; base += gridDim.x * 64) {
        int nrem = min(64, Nn - base);

        float acc[2][8][4];
#pragma unroll
        for (int mb = 0; mb < 2; mb++)
#pragma unroll
            for (int nb = 0; nb < 8; nb++)
#pragma unroll
                for (int q = 0; q < 4; q++) acc[mb][nb][q] = 0.f;

        for (int kc = 0; kc < 8; kc++) {
            __syncthreads();
            {   // weights chunk via cp.async
                const float4* wsrc = (const float4*)(g_wT1 + kc * 4096);
                float4* wdst = (float4*)wS;
                for (int i4 = tid; i4 < 1024; i4 += 128) cpa16(&wdst[i4], &wsrc[i4]);
            }
            if (kc < 4) {
                // agg half: pure tf32-rounded copy
                for (int i4 = tid; i4 < 512; i4 += 128) {
                    int n = i4 >> 3;
                    int kq = (i4 & 7) << 2;
                    void* dst = &inS[n * ASTR + kq];
                    const void* src = &g_agg[(size_t)(base + n) * 128 + kc * KC + kq];
                    if (n < nrem) cpa16(dst, src);
                    else          cpa16_zero(dst, src);
                }
            } else {
                for (int i4 = tid; i4 < 512; i4 += 128) {
                    int n = i4 >> 3;
                    int kq = (i4 & 7) << 2;
                    int k = kc * KC + kq - 128;
                    float4 v = make_float4(0.f, 0.f, 0.f, 0.f);
                    if (n < nrem) {
                        v = *(const float4*)&xin[(size_t)(base + n) * 128 + k];
                        v.x = tf32r(v.x); v.y = tf32r(v.y);
                        v.z = tf32r(v.z); v.w = tf32r(v.w);
                    }
                    *(float4*)&inS[n * ASTR + kq] = v;
                }
            }
            cpa_commit_wait();
            __syncthreads();

#pragma unroll
            for (int ks = 0; ks < 4; ks++) {
                int kb = ks * 8;
                u32 b0[8], b1[8];
                int wbase = (kb >> 2) * 512 + wn * 256 + qr * 4 + qk;
#pragma unroll
                for (int nb = 0; nb < 8; nb++) {
                    b0[nb] = __float_as_uint(wS[wbase + nb * 32]);
                    b1[nb] = __float_as_uint(wS[wbase + 512 + nb * 32]);
                }
                u32 a[2][4];
#pragma unroll
                for (int mb = 0; mb < 2; mb++) {
                    int r0 = (wm * 32 + mb * 16 + qr) * ASTR + kb + qk;
                    a[mb][0] = __float_as_uint(inS[r0]);
                    a[mb][1] = __float_as_uint(inS[r0 + 8 * ASTR]);
                    a[mb][2] = __float_as_uint(inS[r0 + 4]);
                    a[mb][3] = __float_as_uint(inS[r0 + 8 * ASTR + 4]);
                }
#pragma unroll
                for (int mb = 0; mb < 2; mb++)
#pragma unroll
                    for (int nb = 0; nb < 8; nb++)
                        mma_tf32(acc[mb][nb], a[mb], b0[nb], b1[nb]);
            }
        }

        // Epilogue: bias, row L2 norm, store, BN partials
        float ssp[2][2] = {{0.f, 0.f}, {0.f, 0.f}};
#pragma unroll
        for (int mb = 0; mb < 2; mb++)
#pragma unroll
            for (int nb = 0; nb < 8; nb++) {
                acc[mb][nb][0] += bp[nb].x; acc[mb][nb][1] += bp[nb].y;
                acc[mb][nb][2] += bp[nb].x; acc[mb][nb][3] += bp[nb].y;
                ssp[mb][0] += acc[mb][nb][0] * acc[mb][nb][0] + acc[mb][nb][1] * acc[mb][nb][1];
                ssp[mb][1] += acc[mb][nb][2] * acc[mb][nb][2] + acc[mb][nb][3] * acc[mb][nb][3];
            }
#pragma unroll
        for (int mb = 0; mb < 2; mb++)
#pragma unroll
            for (int rs = 0; rs < 2; rs++) {
                ssp[mb][rs] += __shfl_xor_sync(0xffffffffu, ssp[mb][rs], 1);
                ssp[mb][rs] += __shfl_xor_sync(0xffffffffu, ssp[mb][rs], 2);
            }
        if (qk == 0) {
#pragma unroll
            for (int mb = 0; mb < 2; mb++)
#pragma unroll
                for (int rs = 0; rs < 2; rs++)
                    ssS[wn][wm * 32 + mb * 16 + rs * 8 + qr] = ssp[mb][rs];
        }
        __syncthreads();
        float inv[2][2];
#pragma unroll
        for (int mb = 0; mb < 2; mb++)
#pragma unroll
            for (int rs = 0; rs < 2; rs++) {
                int lr = wm * 32 + mb * 16 + rs * 8 + qr;
                float tot = ssS[0][lr] + ssS[1][lr];
                inv[mb][rs] = 1.f / fmaxf(sqrtf(tot), 1e-12f);
            }
#pragma unroll
        for (int mb = 0; mb < 2; mb++) {
            int lr0 = wm * 32 + mb * 16 + qr;
            int lr1 = lr0 + 8;
#pragma unroll
            for (int nb = 0; nb < 8; nb++) {
                int col = wn * 64 + nb * 8 + 2 * qk;
                if (lr0 < nrem) {
                    float vx = acc[mb][nb][0] * inv[mb][0];
                    float vy = acc[mb][nb][1] * inv[mb][0];
                    *(float2*)&g_h[(size_t)(base + lr0) * 128 + col] = make_float2(vx, vy);
                    s1[nb].x += vx; s1[nb].y += vy;
                    s2[nb].x += vx * vx; s2[nb].y += vy * vy;
                }
                if (lr1 < nrem) {
                    float vx = acc[mb][nb][2] * inv[mb][1];
                    float vy = acc[mb][nb][3] * inv[mb][1];
                    *(float2*)&g_h[(size_t)(base + lr1) * 128 + col] = make_float2(vx, vy);
                    s1[nb].x += vx; s1[nb].y += vy;
                    s2[nb].x += vx * vx; s2[nb].y += vy * vy;
                }
            }
        }
        __syncthreads();
    }

    // BN reduction
#pragma unroll
    for (int off = 4; off < 32; off <<= 1) {
#pragma unroll
        for (int nb = 0; nb < 8; nb++) {
            s1[nb].x += __shfl_xor_sync(0xffffffffu, s1[nb].x, off);
            s1[nb].y += __shfl_xor_sync(0xffffffffu, s1[nb].y, off);
            s2[nb].x += __shfl_xor_sync(0xffffffffu, s2[nb].x, off);
            s2[nb].y += __shfl_xor_sync(0xffffffffu, s2[nb].y, off);
        }
    }
    if (lane < 4) {
#pragma unroll
        for (int nb = 0; nb < 8; nb++) {
            int c = wn * 64 + nb * 8 + 2 * lane;
            bnstage[0][warp][c] = s1[nb].x; bnstage[0][warp][c + 1] = s1[nb].y;
            bnstage[1][warp][c] = s2[nb].x; bnstage[1][warp][c + 1] = s2[nb].y;
        }
    }
    __syncthreads();
    if (tid < 128) {
        int wsel = tid >> 6;
        float a0 = bnstage[0][wsel][tid] + bnstage[0][2 + wsel][tid];
        float a1 = bnstage[1][wsel][tid] + bnstage[1][2 + wsel][tid];
        atomicAdd(&g_bnsum[tid], a0);
        atomicAdd(&g_bnsq[tid], a1);
    }
}

__global__ void bn_finalize(const float* __restrict__ gamma, const float* __restrict__ beta, float invN) {
    int c = threadIdx.x;
    float mean = g_bnsum[c] * invN;
    float var = g_bnsq[c] * invN - mean * mean;
    float sc = gamma[c] * rsqrtf(var + 1e-5f);
    g_bnscale[c] = sc;
    g_bnshift[c] = beta[c] - mean * sc;
}

// ---------------------------------------------------------------------------
// GEMM2 (tf32 mma): out[n,c<47] = L2norm_row([agg2 | relu(bn(h))] @ W2 + b2l)
// ---------------------------------------------------------------------------
__global__ void __launch_bounds__(128) sage_gemm2(
    const float* __restrict__ b2l, float* __restrict__ outp, int Nn)
{
    __shared__ float wS[KC * 48];
    __shared__ float inS[64 * ASTR];
    __shared__ float ssS[2][64];

    const int tid  = threadIdx.x;
    const int warp = tid >> 5, lane = tid & 31;
    const int wm = warp >> 1, wn = warp & 1;
    const int qr = lane >> 2, qk = lane & 3;

    float2 bp[3];
#pragma unroll
    for (int nb = 0; nb < 3; nb++) {
        int c = wn * 24 + nb * 8 + 2 * qk;
        bp[nb].x = (c < 47) ? b2l[c] : 0.f;
        bp[nb].y = (c + 1 < 47) ? b2l[c + 1] : 0.f;
    }

    for (int base = blockIdx.x * 64; base < Nn; base += gridDim.x * 64) {
        int nrem = min(64, Nn - base);

        float acc[2][3][4];
#pragma unroll
        for (int mb = 0; mb < 2; mb++)
#pragma unroll
            for (int nb = 0; nb < 3; nb++)
#pragma unroll
                for (int q = 0; q < 4; q++) acc[mb][nb][q] = 0.f;

        for (int kc = 0; kc < 8; kc++) {
            __syncthreads();
            {
                const float4* wsrc = (const float4*)(g_wT2 + kc * 1536);
                float4* wdst = (float4*)wS;
                for (int i4 = tid; i4 < 384; i4 += 128) cpa16(&wdst[i4], &wsrc[i4]);
            }
            if (kc < 4) {
                for (int i4 = tid; i4 < 512; i4 += 128) {
                    int n = i4 >> 3;
                    int kq = (i4 & 7) << 2;
                    void* dst = &inS[n * ASTR + kq];
                    const void* src = &g_agg[(size_t)(base + n) * 128 + kc * KC + kq];
                    if (n < nrem) cpa16(dst, src);
                    else          cpa16_zero(dst, src);
                }
            } else {
                for (int i4 = tid; i4 < 512; i4 += 128) {
                    int n = i4 >> 3;
                    int kq = (i4 & 7) << 2;
                    int c = kc * KC + kq - 128;
                    float4 v = make_float4(0.f, 0.f, 0.f, 0.f);
                    if (n < nrem) {
                        v = *(const float4*)&g_h[(size_t)(base + n) * 128 + c];
                        float4 sc = *(const float4*)&g_bnscale[c];
                        float4 sh = *(const float4*)&g_bnshift[c];
                        v = bnrelu4(v, sc, sh);
                        v.x = tf32r(v.x); v.y = tf32r(v.y);
                        v.z = tf32r(v.z); v.w = tf32r(v.w);
                    }
                    *(float4*)&inS[n * ASTR + kq] = v;
                }
            }
            cpa_commit_wait();
            __syncthreads();

#pragma unroll
            for (int ks = 0; ks < 4; ks++) {
                int kb = ks * 8;
                u32 b0[3], b1[3];
                int wbase = (kb >> 2) * 192 + wn * 96 + qr * 4 + qk;
#pragma unroll
                for (int nb = 0; nb < 3; nb++) {
                    b0[nb] = __float_as_uint(wS[wbase + nb * 32]);
                    b1[nb] = __float_as_uint(wS[wbase + 192 + nb * 32]);
                }
                u32 a[2][4];
#pragma unroll
                for (int mb = 0; mb < 2; mb++) {
                    int r0 = (wm * 32 + mb * 16 + qr) * ASTR + kb + qk;
                    a[mb][0] = __float_as_uint(inS[r0]);
                    a[mb][1] = __float_as_uint(inS[r0 + 8 * ASTR]);
                    a[mb][2] = __float_as_uint(inS[r0 + 4]);
                    a[mb][3] = __float_as_uint(inS[r0 + 8 * ASTR + 4]);
                }
#pragma unroll
                for (int mb = 0; mb < 2; mb++)
#pragma unroll
                    for (int nb = 0; nb < 3; nb++)
                        mma_tf32(acc[mb][nb], a[mb], b0[nb], b1[nb]);
            }
        }

        float ssp[2][2] = {{0.f, 0.f}, {0.f, 0.f}};
#pragma unroll
        for (int mb = 0; mb < 2; mb++)
#pragma unroll
            for (int nb = 0; nb < 3; nb++) {
                acc[mb][nb][0] += bp[nb].x; acc[mb][nb][1] += bp[nb].y;
                acc[mb][nb][2] += bp[nb].x; acc[mb][nb][3] += bp[nb].y;
                ssp[mb][0] += acc[mb][nb][0] * acc[mb][nb][0] + acc[mb][nb][1] * acc[mb][nb][1];
                ssp[mb][1] += acc[mb][nb][2] * acc[mb][nb][2] + acc[mb][nb][3] * acc[mb][nb][3];
            }
#pragma unroll
        for (int mb = 0; mb < 2; mb++)
#pragma unroll
            for (int rs = 0; rs < 2; rs++) {
                ssp[mb][rs] += __shfl_xor_sync(0xffffffffu, ssp[mb][rs], 1);
                ssp[mb][rs] += __shfl_xor_sync(0xffffffffu, ssp[mb][rs], 2);
            }
        if (qk == 0) {
#pragma unroll
            for (int mb = 0; mb < 2; mb++)
#pragma unroll
                for (int rs = 0; rs < 2; rs++)
                    ssS[wn][wm * 32 + mb * 16 + rs * 8 + qr] = ssp[mb][rs];
        }
        __syncthreads();
        float inv[2][2];
#pragma unroll
        for (int mb = 0; mb < 2; mb++)
#pragma unroll
            for (int rs = 0; rs < 2; rs++) {
                int lr = wm * 32 + mb * 16 + rs * 8 + qr;
                float tot = ssS[0][lr] + ssS[1][lr];
                inv[mb][rs] = 1.f / fmaxf(sqrtf(tot), 1e-12f);
            }
#pragma unroll
        for (int mb = 0; mb < 2; mb++) {
            int lr0 = wm * 32 + mb * 16 + qr;
            int lr1 = lr0 + 8;
#pragma unroll
            for (int nb = 0; nb < 3; nb++) {
                int c0 = wn * 24 + nb * 8 + 2 * qk;
                if (lr0 < nrem) {
                    size_t o = (size_t)(base + lr0) * 47;
                    if (c0 < 47)     outp[o + c0]     = acc[mb][nb][0] * inv[mb][0];
                    if (c0 + 1 < 47) outp[o + c0 + 1] = acc[mb][nb][1] * inv[mb][0];
                }
                if (lr1 < nrem) {
                    size_t o = (size_t)(base + lr1) * 47;
                    if (c0 < 47)     outp[o + c0]     = acc[mb][nb][2] * inv[mb][1];
                    if (c0 + 1 < 47) outp[o + c0 + 1] = acc[mb][nb][3] * inv[mb][1];
                }
            }
        }
        __syncthreads();
    }
}

// ---------------------------------------------------------------------------
extern "C" void kernel_launch(void* const* d_in, const int* in_sizes, int n_in,
                              void* d_out, int out_size) {
    const float* x     = (const float*)d_in[0];
    const void*  ei    = d_in[1];
    const float* w1l   = (const float*)d_in[2];
    const float* b1l   = (const float*)d_in[3];
    const float* w1r   = (const float*)d_in[4];
    const float* gamma = (const float*)d_in[5];
    const float* beta  = (const float*)d_in[6];
    const float* w2l   = (const float*)d_in[7];
    const float* b2l   = (const float*)d_in[8];
    const float* w2r   = (const float*)d_in[9];
    int Nn = in_sizes[0] / 128;
    int E  = in_sizes[1] / 2;

    int gb = (Nn + 63) / 64;

    detect_ei<<<1, 32>>>(ei, Nn);
    prep_weights<<<128, 256>>>(w1l, w1r, w2l, w2r, Nn);
    build_adj<<<(E + 255) / 256, 256>>>(ei, E, Nn);
    gather_mean<<<2048, 256>>>(x, 0, Nn);
    sage_gemm1<<<gb, 128>>>(x, b1l, Nn);
    bn_finalize<<<1, 128>>>(gamma, beta, 1.0f / (float)Nn);
    gather_mean<<<2048, 256>>>(nullptr, 1, Nn);
    sage_gemm2<<<gb, 128>>>(b2l, (float*)d_out, Nn);
}

// round 11
// speedup vs baseline: 2.2274x; 1.0580x over previous
#include <cuda_runtime.h>
#include <cstdint>
#include <cstddef>

// ---------------------------------------------------------------------------
// GraphSAGE 2-layer (N=100000, E=800000, 128 -> 128 -> 47, fp32):
//   adjacency build -> gather(writes [agg|self] tf32 row) ->
//   GEMM1(tf32 mma, double-buffered cp.async, +bias+L2norm+BN) -> BN finalize
//   -> gather(+BN+ReLU) -> GEMM2(tf32 mma, double-buffered) -> out
// ---------------------------------------------------------------------------

#define NMAX 100000
#define KC   32
#define ASTR 36
#define SLOTS 64

typedef unsigned long long u64;
typedef unsigned int u32;

__device__ __align__(16) float g_in[(size_t)NMAX * 256];   // [agg | self], tf32
__device__ __align__(16) float g_h[(size_t)NMAX * 128];
__device__ __align__(16) int   g_cnt[NMAX];
__device__ __align__(16) int   g_slot[(size_t)NMAX * SLOTS];
__device__ __align__(16) float g_wT1[256 * 128];   // interleaved [k>>2][c][k&3], tf32
__device__ __align__(16) float g_wT2[256 * 48];
__device__ __align__(16) float g_bnsum[128];
__device__ __align__(16) float g_bnsq[128];
__device__ __align__(16) float g_bnscale[128];
__device__ __align__(16) float g_bnshift[128];
__device__ int g_ei32;

// ---- helpers ---------------------------------------------------------------
__device__ __forceinline__ float tf32r(float x) {
    u32 u;
    asm("cvt.rna.tf32.f32 %0, %1;" : "=r"(u) : "f"(x));
    return __uint_as_float(u);
}
__device__ __forceinline__ void mma_tf32(float* c, const u32* a, u32 b0, u32 b1) {
    asm volatile(
        "mma.sync.aligned.m16n8k8.row.col.f32.tf32.tf32.f32 "
        "{%0,%1,%2,%3}, {%4,%5,%6,%7}, {%8,%9}, {%0,%1,%2,%3};"
        : "+f"(c[0]), "+f"(c[1]), "+f"(c[2]), "+f"(c[3])
        : "r"(a[0]), "r"(a[1]), "r"(a[2]), "r"(a[3]), "r"(b0), "r"(b1));
}
__device__ __forceinline__ void cpa16(void* smem, const void* g) {
    u32 s = (u32)__cvta_generic_to_shared(smem);
    asm volatile("cp.async.cg.shared.global [%0], [%1], 16;" :: "r"(s), "l"(g));
}
__device__ __forceinline__ void cpa16_zero(void* smem, const void* g) {
    u32 s = (u32)__cvta_generic_to_shared(smem);
    asm volatile("cp.async.cg.shared.global [%0], [%1], 16, %2;"
                 :: "r"(s), "l"(g), "r"(0u));
}
__device__ __forceinline__ void cpa_commit() {
    asm volatile("cp.async.commit_group;" ::: "memory");
}
template<int N> __device__ __forceinline__ void cpa_wait() {
    asm volatile("cp.async.wait_group %0;" :: "n"(N) : "memory");
}
__device__ __forceinline__ float4 bnrelu4(float4 v, float4 sc, float4 sh) {
    v.x = fmaxf(fmaf(v.x, sc.x, sh.x), 0.f);
    v.y = fmaxf(fmaf(v.y, sc.y, sh.y), 0.f);
    v.z = fmaxf(fmaf(v.z, sc.z, sh.z), 0.f);
    v.w = fmaxf(fmaf(v.w, sc.w, sh.w), 0.f);
    return v;
}
__device__ __forceinline__ float4 tf32r4(float4 v) {
    v.x = tf32r(v.x); v.y = tf32r(v.y); v.z = tf32r(v.z); v.w = tf32r(v.w);
    return v;
}

// ---------------------------------------------------------------------------
__global__ void detect_ei(const void* ei, int Nn) {
    int lane = threadIdx.x & 31;
    long long v = ((const long long*)ei)[lane & 15];
    unsigned bad = __ballot_sync(0xffffffffu, v < 0 || v >= (long long)Nn);
    if (lane == 0 && blockIdx.x == 0) g_ei32 = bad ? 1 : 0;
}

__global__ void prep_weights(const float* __restrict__ w1l, const float* __restrict__ w1r,
                             const float* __restrict__ w2l, const float* __restrict__ w2r,
                             int Nn) {
    int t = blockIdx.x * blockDim.x + threadIdx.x;
    int stride = gridDim.x * blockDim.x;
    if (t < 256 * 128) {
        int k = t >> 7, c = t & 127;
        float v = (k < 128) ? w1l[c * 128 + k] : w1r[c * 128 + (k - 128)];
        g_wT1[(k >> 2) * 512 + c * 4 + (k & 3)] = tf32r(v);
    }
    if (t < 256 * 48) {
        int k = t / 48, c = t - k * 48;
        float v = 0.f;
        if (c < 47) v = (k < 128) ? w2l[c * 128 + k] : w2r[c * 128 + (k - 128)];
        g_wT2[(k >> 2) * 192 + c * 4 + (k & 3)] = tf32r(v);
    }
    for (int j = t; j < Nn; j += stride) g_cnt[j] = 0;
    if (t < 128) { g_bnsum[t] = 0.f; g_bnsq[t] = 0.f; }
}

__global__ void __launch_bounds__(256) build_adj(
    const void* __restrict__ ei, int E, int Nn)
{
    const int is32 = g_ei32;
    int t = blockIdx.x * blockDim.x + threadIdx.x;
    int stride = gridDim.x * blockDim.x;
    for (int e = t; e < E; e += stride) {
        int src, dst;
        if (is32) {
            src = ((const int*)ei)[e];
            dst = ((const int*)ei)[(size_t)E + e];
        } else {
            src = (int)((const long long*)ei)[e];
            dst = (int)((const long long*)ei)[(size_t)E + e];
        }
        if ((unsigned)src >= (unsigned)Nn || (unsigned)dst >= (unsigned)Nn) continue;
        int pos = atomicAdd(&g_cnt[dst], 1);
        if (pos < SLOTS) g_slot[(size_t)dst * SLOTS + pos] = src;
    }
}

// Gather: one warp per node; lane owns channels 4l..4l+3.
// Writes g_in[n] = [ tf32(mean-agg) | tf32(self) ]  (self = bnrelu(h) if withBN).
__global__ void __launch_bounds__(256, 6) gather_mean(
    const float4* __restrict__ feat4, int withBN, int Nn)
{
    if (withBN) feat4 = (const float4*)g_h;
    int gw   = (blockIdx.x * blockDim.x + threadIdx.x) >> 5;
    int lane = threadIdx.x & 31;
    int nw   = (gridDim.x * blockDim.x) >> 5;
    float4 sc = make_float4(1.f, 1.f, 1.f, 1.f);
    float4 sh = make_float4(0.f, 0.f, 0.f, 0.f);
    if (withBN) {
        sc = ((const float4*)g_bnscale)[lane];
        sh = ((const float4*)g_bnshift)[lane];
    }
    float4* out4 = (float4*)g_in;
    for (int n = gw; n < Nn; n += nw) {
        int cnt = g_cnt[n];
        int m = min(cnt, SLOTS);
        const int* sl = g_slot + (size_t)n * SLOTS;
        float4 a = make_float4(0.f, 0.f, 0.f, 0.f);
        int j = 0;
        for (; j + 4 <= m; j += 4) {
            int s0 = sl[j], s1 = sl[j + 1], s2 = sl[j + 2], s3 = sl[j + 3];
            float4 v0 = feat4[(size_t)s0 * 32 + lane];
            float4 v1 = feat4[(size_t)s1 * 32 + lane];
            float4 v2 = feat4[(size_t)s2 * 32 + lane];
            float4 v3 = feat4[(size_t)s3 * 32 + lane];
            if (withBN) {
                v0 = bnrelu4(v0, sc, sh); v1 = bnrelu4(v1, sc, sh);
                v2 = bnrelu4(v2, sc, sh); v3 = bnrelu4(v3, sc, sh);
            }
            a.x += (v0.x + v1.x) + (v2.x + v3.x);
            a.y += (v0.y + v1.y) + (v2.y + v3.y);
            a.z += (v0.z + v1.z) + (v2.z + v3.z);
            a.w += (v0.w + v1.w) + (v2.w + v3.w);
        }
        for (; j < m; j++) {
            float4 v = feat4[(size_t)sl[j] * 32 + lane];
            if (withBN) v = bnrelu4(v, sc, sh);
            a.x += v.x; a.y += v.y; a.z += v.z; a.w += v.w;
        }
        float r = 1.f / fmaxf((float)cnt, 1.f);
        a.x *= r; a.y *= r; a.z *= r; a.w *= r;
        out4[(size_t)n * 64 + lane] = tf32r4(a);
        float4 s = feat4[(size_t)n * 32 + lane];
        if (withBN) s = bnrelu4(s, sc, sh);
        out4[(size_t)n * 64 + 32 + lane] = tf32r4(s);
    }
}

// ---------------------------------------------------------------------------
// GEMM1 (tf32 mma, 2-stage cp.async pipeline): h = L2norm_row(g_in @ W1 + b1l)
// 128 threads, 64-node x 128-ch tile; dynamic smem 2x(16KB wS + 9KB inS).
// ---------------------------------------------------------------------------
__global__ void __launch_bounds__(128) sage_gemm1(
    const float* __restrict__ bias, int Nn)
{
    extern __shared__ float dyn[];
    float* wSb = dyn;            // 2 * 4096
    float* iSb = dyn + 8192;     // 2 * 2304
    __shared__ float ssS[2][64];
    __shared__ float bnstage[2][4][128];

    const int tid  = threadIdx.x;
    const int warp = tid >> 5, lane = tid & 31;
    const int wm = warp >> 1, wn = warp & 1;
    const int qr = lane >> 2, qk = lane & 3;

    float2 bp[8];
#pragma unroll
    for (int nb = 0; nb < 8; nb++)
        bp[nb] = *(const float2*)&bias[wn * 64 + nb * 8 + 2 * qk];

    float2 s1[8], s2[8];
#pragma unroll
    for (int nb = 0; nb < 8; nb++) { s1[nb] = make_float2(0.f, 0.f); s2[nb] = make_float2(0.f, 0.f); }

    for (int base = blockIdx.x * 64; base < Nn; base += gridDim.x * 64) {
        int nrem = min(64, Nn - base);

        float acc[2][8][4];
#pragma unroll
        for (int mb = 0; mb < 2; mb++)
#pragma unroll
            for (int nb = 0; nb < 8; nb++)
#pragma unroll
                for (int q = 0; q < 4; q++) acc[mb][nb][q] = 0.f;

        // stage a chunk: weights 1024 f4, inputs 512 f4 (pure cp.async)
        auto stage = [&](int kc, int buf) {
            float4* wdst = (float4*)(wSb + buf * 4096);
            const float4* wsrc = (const float4*)(g_wT1 + kc * 4096);
            for (int i4 = tid; i4 < 1024; i4 += 128) cpa16(&wdst[i4], &wsrc[i4]);
            float* ib = iSb + buf * 2304;
            for (int i4 = tid; i4 < 512; i4 += 128) {
                int n = i4 >> 3;
                int kq4 = (i4 & 7) << 2;
                void* dst = &ib[n * ASTR + kq4];
                const void* src = &g_in[(size_t)(base + n) * 256 + kc * KC + kq4];
                if (n < nrem) cpa16(dst, src);
                else          cpa16_zero(dst, g_in);
            }
        };

        stage(0, 0);
        cpa_commit();
        for (int kc = 0; kc < 8; kc++) {
            int cur = kc & 1;
            if (kc < 7) { stage(kc + 1, cur ^ 1); cpa_commit(); cpa_wait<1>(); }
            else        { cpa_wait<0>(); }
            __syncthreads();

            const float* wS = wSb + cur * 4096;
            const float* inS = iSb + cur * 2304;
#pragma unroll
            for (int ks = 0; ks < 4; ks++) {
                int kb = ks * 8;
                u32 b0[8], b1[8];
                int wbase = (kb >> 2) * 512 + wn * 256 + qr * 4 + qk;
#pragma unroll
                for (int nb = 0; nb < 8; nb++) {
                    b0[nb] = __float_as_uint(wS[wbase + nb * 32]);
                    b1[nb] = __float_as_uint(wS[wbase + 512 + nb * 32]);
                }
                u32 a[2][4];
#pragma unroll
                for (int mb = 0; mb < 2; mb++) {
                    int r0 = (wm * 32 + mb * 16 + qr) * ASTR + kb + qk;
                    a[mb][0] = __float_as_uint(inS[r0]);
                    a[mb][1] = __float_as_uint(inS[r0 + 8 * ASTR]);
                    a[mb][2] = __float_as_uint(inS[r0 + 4]);
                    a[mb][3] = __float_as_uint(inS[r0 + 8 * ASTR + 4]);
                }
#pragma unroll
                for (int mb = 0; mb < 2; mb++)
#pragma unroll
                    for (int nb = 0; nb < 8; nb++)
                        mma_tf32(acc[mb][nb], a[mb], b0[nb], b1[nb]);
            }
            __syncthreads();
        }

        // Epilogue: bias, row L2 norm, store h, BN partials
        float ssp[2][2] = {{0.f, 0.f}, {0.f, 0.f}};
#pragma unroll
        for (int mb = 0; mb < 2; mb++)
#pragma unroll
            for (int nb = 0; nb < 8; nb++) {
                acc[mb][nb][0] += bp[nb].x; acc[mb][nb][1] += bp[nb].y;
                acc[mb][nb][2] += bp[nb].x; acc[mb][nb][3] += bp[nb].y;
                ssp[mb][0] += acc[mb][nb][0] * acc[mb][nb][0] + acc[mb][nb][1] * acc[mb][nb][1];
                ssp[mb][1] += acc[mb][nb][2] * acc[mb][nb][2] + acc[mb][nb][3] * acc[mb][nb][3];
            }
#pragma unroll
        for (int mb = 0; mb < 2; mb++)
#pragma unroll
            for (int rs = 0; rs < 2; rs++) {
                ssp[mb][rs] += __shfl_xor_sync(0xffffffffu, ssp[mb][rs], 1);
                ssp[mb][rs] += __shfl_xor_sync(0xffffffffu, ssp[mb][rs], 2);
            }
        if (qk == 0) {
#pragma unroll
            for (int mb = 0; mb < 2; mb++)
#pragma unroll
                for (int rs = 0; rs < 2; rs++)
                    ssS[wn][wm * 32 + mb * 16 + rs * 8 + qr] = ssp[mb][rs];
        }
        __syncthreads();
        float inv[2][2];
#pragma unroll
        for (int mb = 0; mb < 2; mb++)
#pragma unroll
            for (int rs = 0; rs < 2; rs++) {
                int lr = wm * 32 + mb * 16 + rs * 8 + qr;
                float tot = ssS[0][lr] + ssS[1][lr];
                inv[mb][rs] = 1.f / fmaxf(sqrtf(tot), 1e-12f);
            }
#pragma unroll
        for (int mb = 0; mb < 2; mb++) {
            int lr0 = wm * 32 + mb * 16 + qr;
            int lr1 = lr0 + 8;
#pragma unroll
            for (int nb = 0; nb < 8; nb++) {
                int col = wn * 64 + nb * 8 + 2 * qk;
                if (lr0 < nrem) {
                    float vx = acc[mb][nb][0] * inv[mb][0];
                    float vy = acc[mb][nb][1] * inv[mb][0];
                    *(float2*)&g_h[(size_t)(base + lr0) * 128 + col] = make_float2(vx, vy);
                    s1[nb].x += vx; s1[nb].y += vy;
                    s2[nb].x += vx * vx; s2[nb].y += vy * vy;
                }
                if (lr1 < nrem) {
                    float vx = acc[mb][nb][2] * inv[mb][1];
                    float vy = acc[mb][nb][3] * inv[mb][1];
                    *(float2*)&g_h[(size_t)(base + lr1) * 128 + col] = make_float2(vx, vy);
                    s1[nb].x += vx; s1[nb].y += vy;
                    s2[nb].x += vx * vx; s2[nb].y += vy * vy;
                }
            }
        }
        __syncthreads();
    }

    // BN reduction
#pragma unroll
    for (int off = 4; off < 32; off <<= 1) {
#pragma unroll
        for (int nb = 0; nb < 8; nb++) {
            s1[nb].x += __shfl_xor_sync(0xffffffffu, s1[nb].x, off);
            s1[nb].y += __shfl_xor_sync(0xffffffffu, s1[nb].y, off);
            s2[nb].x += __shfl_xor_sync(0xffffffffu, s2[nb].x, off);
            s2[nb].y += __shfl_xor_sync(0xffffffffu, s2[nb].y, off);
        }
    }
    if (lane < 4) {
#pragma unroll
        for (int nb = 0; nb < 8; nb++) {
            int c = wn * 64 + nb * 8 + 2 * lane;
            bnstage[0][warp][c] = s1[nb].x; bnstage[0][warp][c + 1] = s1[nb].y;
            bnstage[1][warp][c] = s2[nb].x; bnstage[1][warp][c + 1] = s2[nb].y;
        }
    }
    __syncthreads();
    if (tid < 128) {
        int wsel = tid >> 6;
        float a0 = bnstage[0][wsel][tid] + bnstage[0][2 + wsel][tid];
        float a1 = bnstage[1][wsel][tid] + bnstage[1][2 + wsel][tid];
        atomicAdd(&g_bnsum[tid], a0);
        atomicAdd(&g_bnsq[tid], a1);
    }
}

__global__ void bn_finalize(const float* __restrict__ gamma, const float* __restrict__ beta, float invN) {
    int c = threadIdx.x;
    float mean = g_bnsum[c] * invN;
    float var = g_bnsq[c] * invN - mean * mean;
    float sc = gamma[c] * rsqrtf(var + 1e-5f);
    g_bnscale[c] = sc;
    g_bnshift[c] = beta[c] - mean * sc;
}

// ---------------------------------------------------------------------------
// GEMM2 (tf32 mma, 2-stage pipeline): out = L2norm_row(g_in @ W2 + b2l)
// ---------------------------------------------------------------------------
__global__ void __launch_bounds__(128) sage_gemm2(
    const float* __restrict__ b2l, float* __restrict__ outp, int Nn)
{
    extern __shared__ float dyn[];
    float* wSb = dyn;            // 2 * 1536
    float* iSb = dyn + 3072;     // 2 * 2304
    __shared__ float ssS[2][64];

    const int tid  = threadIdx.x;
    const int warp = tid >> 5, lane = tid & 31;
    const int wm = warp >> 1, wn = warp & 1;
    const int qr = lane >> 2, qk = lane & 3;

    float2 bp[3];
#pragma unroll
    for (int nb = 0; nb < 3; nb++) {
        int c = wn * 24 + nb * 8 + 2 * qk;
        bp[nb].x = (c < 47) ? b2l[c] : 0.f;
        bp[nb].y = (c + 1 < 47) ? b2l[c + 1] : 0.f;
    }

    for (int base = blockIdx.x * 64; base < Nn; base += gridDim.x * 64) {
        int nrem = min(64, Nn - base);

        float acc[2][3][4];
#pragma unroll
        for (int mb = 0; mb < 2; mb++)
#pragma unroll
            for (int nb = 0; nb < 3; nb++)
#pragma unroll
                for (int q = 0; q < 4; q++) acc[mb][nb][q] = 0.f;

        auto stage = [&](int kc, int buf) {
            float4* wdst = (float4*)(wSb + buf * 1536);
            const float4* wsrc = (const float4*)(g_wT2 + kc * 1536);
            for (int i4 = tid; i4 < 384; i4 += 128) cpa16(&wdst[i4], &wsrc[i4]);
            float* ib = iSb + buf * 2304;
            for (int i4 = tid; i4 < 512; i4 += 128) {
                int n = i4 >> 3;
                int kq4 = (i4 & 7) << 2;
                void* dst = &ib[n * ASTR + kq4];
                const void* src = &g_in[(size_t)(base + n) * 256 + kc * KC + kq4];
                if (n < nrem) cpa16(dst, src);
                else          cpa16_zero(dst, g_in);
            }
        };

        stage(0, 0);
        cpa_commit();
        for (int kc = 0; kc < 8; kc++) {
            int cur = kc & 1;
            if (kc < 7) { stage(kc + 1, cur ^ 1); cpa_commit(); cpa_wait<1>(); }
            else        { cpa_wait<0>(); }
            __syncthreads();

            const float* wS = wSb + cur * 1536;
            const float* inS = iSb + cur * 2304;
#pragma unroll
            for (int ks = 0; ks < 4; ks++) {
                int kb = ks * 8;
                u32 b0[3], b1[3];
                int wbase = (kb >> 2) * 192 + wn * 96 + qr * 4 + qk;
#pragma unroll
                for (int nb = 0; nb < 3; nb++) {
                    b0[nb] = __float_as_uint(wS[wbase + nb * 32]);
                    b1[nb] = __float_as_uint(wS[wbase + 192 + nb * 32]);
                }
                u32 a[2][4];
#pragma unroll
                for (int mb = 0; mb < 2; mb++) {
                    int r0 = (wm * 32 + mb * 16 + qr) * ASTR + kb + qk;
                    a[mb][0] = __float_as_uint(inS[r0]);
                    a[mb][1] = __float_as_uint(inS[r0 + 8 * ASTR]);
                    a[mb][2] = __float_as_uint(inS[r0 + 4]);
                    a[mb][3] = __float_as_uint(inS[r0 + 8 * ASTR + 4]);
                }
#pragma unroll
                for (int mb = 0; mb < 2; mb++)
#pragma unroll
                    for (int nb = 0; nb < 3; nb++)
                        mma_tf32(acc[mb][nb], a[mb], b0[nb], b1[nb]);
            }
            __syncthreads();
        }

        float ssp[2][2] = {{0.f, 0.f}, {0.f, 0.f}};
#pragma unroll
        for (int mb = 0; mb < 2; mb++)
#pragma unroll
            for (int nb = 0; nb < 3; nb++) {
                acc[mb][nb][0] += bp[nb].x; acc[mb][nb][1] += bp[nb].y;
                acc[mb][nb][2] += bp[nb].x; acc[mb][nb][3] += bp[nb].y;
                ssp[mb][0] += acc[mb][nb][0] * acc[mb][nb][0] + acc[mb][nb][1] * acc[mb][nb][1];
                ssp[mb][1] += acc[mb][nb][2] * acc[mb][nb][2] + acc[mb][nb][3] * acc[mb][nb][3];
            }
#pragma unroll
        for (int mb = 0; mb < 2; mb++)
#pragma unroll
            for (int rs = 0; rs < 2; rs++) {
                ssp[mb][rs] += __shfl_xor_sync(0xffffffffu, ssp[mb][rs], 1);
                ssp[mb][rs] += __shfl_xor_sync(0xffffffffu, ssp[mb][rs], 2);
            }
        if (qk == 0) {
#pragma unroll
            for (int mb = 0; mb < 2; mb++)
#pragma unroll
                for (int rs = 0; rs < 2; rs++)
                    ssS[wn][wm * 32 + mb * 16 + rs * 8 + qr] = ssp[mb][rs];
        }
        __syncthreads();
        float inv[2][2];
#pragma unroll
        for (int mb = 0; mb < 2; mb++)
#pragma unroll
            for (int rs = 0; rs < 2; rs++) {
                int lr = wm * 32 + mb * 16 + rs * 8 + qr;
                float tot = ssS[0][lr] + ssS[1][lr];
                inv[mb][rs] = 1.f / fmaxf(sqrtf(tot), 1e-12f);
            }
#pragma unroll
        for (int mb = 0; mb < 2; mb++) {
            int lr0 = wm * 32 + mb * 16 + qr;
            int lr1 = lr0 + 8;
#pragma unroll
            for (int nb = 0; nb < 3; nb++) {
                int c0 = wn * 24 + nb * 8 + 2 * qk;
                if (lr0 < nrem) {
                    size_t o = (size_t)(base + lr0) * 47;
                    if (c0 < 47)     outp[o + c0]     = acc[mb][nb][0] * inv[mb][0];
                    if (c0 + 1 < 47) outp[o + c0 + 1] = acc[mb][nb][1] * inv[mb][0];
                }
                if (lr1 < nrem) {
                    size_t o = (size_t)(base + lr1) * 47;
                    if (c0 < 47)     outp[o + c0]     = acc[mb][nb][2] * inv[mb][1];
                    if (c0 + 1 < 47) outp[o + c0 + 1] = acc[mb][nb][3] * inv[mb][1];
                }
            }
        }
        __syncthreads();
    }
}

// ---------------------------------------------------------------------------
extern "C" void kernel_launch(void* const* d_in, const int* in_sizes, int n_in,
                              void* d_out, int out_size) {
    const float* x     = (const float*)d_in[0];
    const void*  ei    = d_in[1];
    const float* w1l   = (const float*)d_in[2];
    const float* b1l   = (const float*)d_in[3];
    const float* w1r   = (const float*)d_in[4];
    const float* gamma = (const float*)d_in[5];
    const float* beta  = (const float*)d_in[6];
    const float* w2l   = (const float*)d_in[7];
    const float* b2l   = (const float*)d_in[8];
    const float* w2r   = (const float*)d_in[9];
    int Nn = in_sizes[0] / 128;
    int E  = in_sizes[1] / 2;

    int gb = (Nn + 63) / 64;
    int smem1 = (2 * 4096 + 2 * 2304) * 4;   // 51200 B
    int smem2 = (2 * 1536 + 2 * 2304) * 4;   // 30720 B

    static int attr_done = 0;
    if (!attr_done) {
        cudaFuncSetAttribute(sage_gemm1, cudaFuncAttributeMaxDynamicSharedMemorySize, smem1);
        attr_done = 1;
    }

    detect_ei<<<1, 32>>>(ei, Nn);
    prep_weights<<<128, 256>>>(w1l, w1r, w2l, w2r, Nn);
    build_adj<<<(E + 255) / 256, 256>>>(ei, E, Nn);
    gather_mean<<<2048, 256>>>((const float4*)x, 0, Nn);
    sage_gemm1<<<gb, 128, smem1>>>(b1l, Nn);
    bn_finalize<<<1, 128>>>(gamma, beta, 1.0f / (float)Nn);
    gather_mean<<<2048, 256>>>(nullptr, 1, Nn);
    sage_gemm2<<<gb, 128, smem2>>>(b2l, (float*)d_out, Nn);
}

// round 13
// speedup vs baseline: 2.8451x; 1.2773x over previous
#include <cuda_runtime.h>
#include <cuda_fp16.h>
#include <cstdint>
#include <cstddef>

// ---------------------------------------------------------------------------
// GraphSAGE 2-layer (N=100000, E=800000, 128 -> 128 -> 47, fp32 in/out):
//   x -> fp16 convert -> adjacency build -> gather([agg|self] fp16 row) ->
//   GEMM1(fp16 mma m16n8k16, double-buffered cp.async, +bias+L2norm+BN,
//   h stored fp16) -> BN finalize -> gather(+BN+ReLU) -> GEMM2(fp16 mma) -> out
// All feature traffic fp16 (same 10-bit mantissa as tf32); accum fp32.
// NOTE: device-global pointers are selected INSIDE kernels (host-side
// addresses of __device__ symbols are invalid; on GB300 ATS they silently
// read host memory instead of faulting — cause of the R12 failure).
// ---------------------------------------------------------------------------

#define NMAX 100000
#define KC   32          // k per staged chunk (2 x k16 slabs)
#define IWSTR 20         // inS row stride in u32 words (40 halves)
#define SLOTS 64

typedef unsigned long long u64;
typedef unsigned int u32;

__device__ __align__(16) u32  g_x16[(size_t)NMAX * 64];    // x as fp16 (128 halves/row)
__device__ __align__(16) u32  g_h16[(size_t)NMAX * 64];    // h as fp16
__device__ __align__(16) u32  g_in16[(size_t)NMAX * 128];  // [agg|self] fp16 (256 halves/row)
__device__ __align__(16) int  g_cnt[NMAX];
__device__ __align__(16) int  g_slot[(size_t)NMAX * SLOTS];
__device__ __align__(16) u32  g_wT1h[16384];  // fp16 frag-ordered: [kc8][ks2][nb16][64]
__device__ __align__(16) u32  g_wT2h[6144];   // [kc8][ks2][nb6][64] (48 cols padded)
__device__ __align__(16) float g_bnsum[128];
__device__ __align__(16) float g_bnsq[128];
__device__ __align__(16) float g_bnscale[128];
__device__ __align__(16) float g_bnshift[128];
__device__ int g_ei32;

// ---- helpers ---------------------------------------------------------------
__device__ __forceinline__ void mma_f16(float* c, u32 a0, u32 a1, u32 a2, u32 a3,
                                        u32 b0, u32 b1) {
    asm volatile(
        "mma.sync.aligned.m16n8k16.row.col.f32.f16.f16.f32 "
        "{%0,%1,%2,%3}, {%4,%5,%6,%7}, {%8,%9}, {%0,%1,%2,%3};"
        : "+f"(c[0]), "+f"(c[1]), "+f"(c[2]), "+f"(c[3])
        : "r"(a0), "r"(a1), "r"(a2), "r"(a3), "r"(b0), "r"(b1));
}
__device__ __forceinline__ void cpa16(void* smem, const void* g) {
    u32 s = (u32)__cvta_generic_to_shared(smem);
    asm volatile("cp.async.cg.shared.global [%0], [%1], 16;" :: "r"(s), "l"(g));
}
__device__ __forceinline__ void cpa16_zero(void* smem, const void* g) {
    u32 s = (u32)__cvta_generic_to_shared(smem);
    asm volatile("cp.async.cg.shared.global [%0], [%1], 16, %2;"
                 :: "r"(s), "l"(g), "r"(0u));
}
__device__ __forceinline__ void cpa_commit() {
    asm volatile("cp.async.commit_group;" ::: "memory");
}
template<int N> __device__ __forceinline__ void cpa_wait() {
    asm volatile("cp.async.wait_group %0;" :: "n"(N) : "memory");
}
__device__ __forceinline__ float4 bnrelu4(float4 v, float4 sc, float4 sh) {
    v.x = fmaxf(fmaf(v.x, sc.x, sh.x), 0.f);
    v.y = fmaxf(fmaf(v.y, sc.y, sh.y), 0.f);
    v.z = fmaxf(fmaf(v.z, sc.z, sh.z), 0.f);
    v.w = fmaxf(fmaf(v.w, sc.w, sh.w), 0.f);
    return v;
}
__device__ __forceinline__ float4 unpack_h4(uint2 u) {
    float2 f0 = __half22float2(*reinterpret_cast<__half2*>(&u.x));
    float2 f1 = __half22float2(*reinterpret_cast<__half2*>(&u.y));
    return make_float4(f0.x, f0.y, f1.x, f1.y);
}
__device__ __forceinline__ uint2 pack_h4(float4 v) {
    __half2 p0 = __floats2half2_rn(v.x, v.y);
    __half2 p1 = __floats2half2_rn(v.z, v.w);
    uint2 o;
    o.x = *reinterpret_cast<u32*>(&p0);
    o.y = *reinterpret_cast<u32*>(&p1);
    return o;
}

// ---------------------------------------------------------------------------
__global__ void detect_ei(const void* ei, int Nn) {
    int lane = threadIdx.x & 31;
    long long v = ((const long long*)ei)[lane & 15];
    unsigned bad = __ballot_sync(0xffffffffu, v < 0 || v >= (long long)Nn);
    if (lane == 0 && blockIdx.x == 0) g_ei32 = bad ? 1 : 0;
}

// Weights -> fp16, MMA-fragment-ordered; zero cnt/BN accumulators.
// W1 word dest: kc*2048 + ks*1024 + nb*64 + hs*32 + cib*4 + t
//   holds half2( W[col][k0], W[col][k0+1] ), col=nb*8+cib, k0=(kc*2+ks)*16+2t+hs*8
__global__ void prep_all(const float* __restrict__ w1l, const float* __restrict__ w1r,
                         const float* __restrict__ w2l, const float* __restrict__ w2r,
                         int Nn) {
    int t = blockIdx.x * blockDim.x + threadIdx.x;
    int stride = gridDim.x * blockDim.x;
    for (int w = t; w < 16384; w += stride) {
        int kk = w >> 10;            // k16 slab 0..15
        int r = w & 1023;
        int nb = r >> 6;
        int r2 = r & 63;
        int hs = r2 >> 5;
        int r3 = r2 & 31;
        int cib = r3 >> 2;
        int tt = r3 & 3;
        int col = nb * 8 + cib;
        int k0 = kk * 16 + 2 * tt + hs * 8;
        float v0 = (k0 < 128) ? w1l[col * 128 + k0] : w1r[col * 128 + k0 - 128];
        int k1 = k0 + 1;
        float v1 = (k1 < 128) ? w1l[col * 128 + k1] : w1r[col * 128 + k1 - 128];
        __half2 h = __floats2half2_rn(v0, v1);
        int dest = (kk >> 1) * 2048 + (kk & 1) * 1024 + nb * 64 + hs * 32 + cib * 4 + tt;
        g_wT1h[dest] = *reinterpret_cast<u32*>(&h);
    }
    for (int w = t; w < 6144; w += stride) {
        int kk = w / 384;
        int r = w - kk * 384;
        int nb = r >> 6;
        int r2 = r & 63;
        int hs = r2 >> 5;
        int r3 = r2 & 31;
        int cib = r3 >> 2;
        int tt = r3 & 3;
        int col = nb * 8 + cib;
        int k0 = kk * 16 + 2 * tt + hs * 8;
        float v0 = 0.f, v1 = 0.f;
        if (col < 47) {
            v0 = (k0 < 128) ? w2l[col * 128 + k0] : w2r[col * 128 + k0 - 128];
            v1 = (k0 + 1 < 128) ? w2l[col * 128 + k0 + 1] : w2r[col * 128 + k0 + 1 - 128];
        }
        __half2 h = __floats2half2_rn(v0, v1);
        int dest = (kk >> 1) * 768 + (kk & 1) * 384 + nb * 64 + hs * 32 + cib * 4 + tt;
        g_wT2h[dest] = *reinterpret_cast<u32*>(&h);
    }
    for (int j = t; j < Nn; j += stride) g_cnt[j] = 0;
    if (t < 128) { g_bnsum[t] = 0.f; g_bnsq[t] = 0.f; }
}

// x (fp32) -> g_x16 (fp16). One thread per float4.
__global__ void __launch_bounds__(256) convert_x(const float4* __restrict__ x4, int n4) {
    int i = blockIdx.x * blockDim.x + threadIdx.x;
    int stride = gridDim.x * blockDim.x;
    uint2* out = (uint2*)g_x16;
    for (int j = i; j < n4; j += stride) out[j] = pack_h4(x4[j]);
}

__global__ void __launch_bounds__(256) build_adj(
    const void* __restrict__ ei, int E, int Nn)
{
    const int is32 = g_ei32;
    int t = blockIdx.x * blockDim.x + threadIdx.x;
    int stride = gridDim.x * blockDim.x;
    for (int e = t; e < E; e += stride) {
        int src, dst;
        if (is32) {
            src = ((const int*)ei)[e];
            dst = ((const int*)ei)[(size_t)E + e];
        } else {
            src = (int)((const long long*)ei)[e];
            dst = (int)((const long long*)ei)[(size_t)E + e];
        }
        if ((unsigned)src >= (unsigned)Nn || (unsigned)dst >= (unsigned)Nn) continue;
        int pos = atomicAdd(&g_cnt[dst], 1);
        if (pos < SLOTS) g_slot[(size_t)dst * SLOTS + pos] = src;
    }
}

// Gather: one warp per node; lane owns channels 4l..4l+3 (one uint2 = 4 halves).
// srcSel: 0 -> g_x16 (layer 1), 1 -> g_h16 with BN+ReLU (layer 2).
// Writes g_in16[n] = [ mean-agg | self ], fp16.
__global__ void __launch_bounds__(256, 6) gather_mean(int srcSel, int Nn)
{
    const uint2* feat2 = srcSel ? (const uint2*)g_h16 : (const uint2*)g_x16;
    const int withBN = srcSel;
    int gw   = (blockIdx.x * blockDim.x + threadIdx.x) >> 5;
    int lane = threadIdx.x & 31;
    int nw   = (gridDim.x * blockDim.x) >> 5;
    float4 sc = make_float4(1.f, 1.f, 1.f, 1.f);
    float4 sh = make_float4(0.f, 0.f, 0.f, 0.f);
    if (withBN) {
        sc = ((const float4*)g_bnscale)[lane];
        sh = ((const float4*)g_bnshift)[lane];
    }
    uint2* out2 = (uint2*)g_in16;
    for (int n = gw; n < Nn; n += nw) {
        int cnt = g_cnt[n];
        int m = min(cnt, SLOTS);
        const int* sl = g_slot + (size_t)n * SLOTS;
        float4 a = make_float4(0.f, 0.f, 0.f, 0.f);
        int j = 0;
        for (; j + 4 <= m; j += 4) {
            float4 v0 = unpack_h4(feat2[(size_t)sl[j]     * 32 + lane]);
            float4 v1 = unpack_h4(feat2[(size_t)sl[j + 1] * 32 + lane]);
            float4 v2 = unpack_h4(feat2[(size_t)sl[j + 2] * 32 + lane]);
            float4 v3 = unpack_h4(feat2[(size_t)sl[j + 3] * 32 + lane]);
            if (withBN) {
                v0 = bnrelu4(v0, sc, sh); v1 = bnrelu4(v1, sc, sh);
                v2 = bnrelu4(v2, sc, sh); v3 = bnrelu4(v3, sc, sh);
            }
            a.x += (v0.x + v1.x) + (v2.x + v3.x);
            a.y += (v0.y + v1.y) + (v2.y + v3.y);
            a.z += (v0.z + v1.z) + (v2.z + v3.z);
            a.w += (v0.w + v1.w) + (v2.w + v3.w);
        }
        for (; j < m; j++) {
            float4 v = unpack_h4(feat2[(size_t)sl[j] * 32 + lane]);
            if (withBN) v = bnrelu4(v, sc, sh);
            a.x += v.x; a.y += v.y; a.z += v.z; a.w += v.w;
        }
        float r = 1.f / fmaxf((float)cnt, 1.f);
        a.x *= r; a.y *= r; a.z *= r; a.w *= r;
        out2[(size_t)n * 64 + lane] = pack_h4(a);
        float4 s = unpack_h4(feat2[(size_t)n * 32 + lane]);
        if (withBN) s = bnrelu4(s, sc, sh);
        out2[(size_t)n * 64 + 32 + lane] = pack_h4(s);
    }
}

// ---------------------------------------------------------------------------
// GEMM1 (fp16 mma m16n8k16, 2-stage cp.async): h = L2norm_row(g_in @ W1 + b1l)
// 128 threads = 4 warps (wm,wn 2x2); 64-node x 128-ch tile.
// ---------------------------------------------------------------------------
__global__ void __launch_bounds__(128) sage_gemm1(
    const float* __restrict__ bias, int Nn)
{
    extern __shared__ u32 dyn[];
    u32* wSb = dyn;            // 2 * 2048
    u32* iSb = dyn + 4096;     // 2 * 1280
    __shared__ float ssS[2][64];
    __shared__ float bnstage[2][4][128];

    const int tid  = threadIdx.x;
    const int warp = tid >> 5, lane = tid & 31;
    const int wm = warp >> 1, wn = warp & 1;
    const int qr = lane >> 2, qk = lane & 3;

    float2 bp[8];
#pragma unroll
    for (int nb = 0; nb < 8; nb++)
        bp[nb] = *(const float2*)&bias[wn * 64 + nb * 8 + 2 * qk];

    float2 s1[8], s2[8];
#pragma unroll
    for (int nb = 0; nb < 8; nb++) { s1[nb] = make_float2(0.f, 0.f); s2[nb] = make_float2(0.f, 0.f); }

    for (int base = blockIdx.x * 64; base < Nn; base += gridDim.x * 64) {
        int nrem = min(64, Nn - base);

        float acc[2][8][4];
#pragma unroll
        for (int mb = 0; mb < 2; mb++)
#pragma unroll
            for (int nb = 0; nb < 8; nb++)
#pragma unroll
                for (int q = 0; q < 4; q++) acc[mb][nb][q] = 0.f;

        auto stage = [&](int kc, int buf) {
            u32* wdst = wSb + buf * 2048;
            const u32* wsrc = g_wT1h + kc * 2048;
            for (int i4 = tid; i4 < 512; i4 += 128) cpa16(&wdst[i4 * 4], &wsrc[i4 * 4]);
            u32* ib = iSb + buf * 1280;
            for (int i = tid; i < 256; i += 128) {
                int n = i >> 2, q = i & 3;
                void* dst = &ib[n * IWSTR + q * 4];
                const void* src = &g_in16[(size_t)(base + n) * 128 + kc * 16 + q * 4];
                if (n < nrem) cpa16(dst, src);
                else          cpa16_zero(dst, g_in16);
            }
        };

        stage(0, 0);
        cpa_commit();
        for (int kc = 0; kc < 8; kc++) {
            int cur = kc & 1;
            if (kc < 7) { stage(kc + 1, cur ^ 1); cpa_commit(); cpa_wait<1>(); }
            else        { cpa_wait<0>(); }
            __syncthreads();

            const u32* wS = wSb + cur * 2048;
            const u32* inS = iSb + cur * 1280;
#pragma unroll
            for (int ks = 0; ks < 2; ks++) {
                u32 b0[8], b1[8];
                int wb0 = ks * 1024 + wn * 512 + qr * 4 + qk;
#pragma unroll
                for (int nb = 0; nb < 8; nb++) {
                    b0[nb] = wS[wb0 + nb * 64];
                    b1[nb] = wS[wb0 + nb * 64 + 32];
                }
                u32 a[2][4];
#pragma unroll
                for (int mb = 0; mb < 2; mb++) {
                    int r0 = (wm * 32 + mb * 16 + qr) * IWSTR + ks * 8 + qk;
                    int r1 = r0 + 8 * IWSTR;
                    a[mb][0] = inS[r0];
                    a[mb][1] = inS[r1];
                    a[mb][2] = inS[r0 + 4];
                    a[mb][3] = inS[r1 + 4];
                }
#pragma unroll
                for (int mb = 0; mb < 2; mb++)
#pragma unroll
                    for (int nb = 0; nb < 8; nb++)
                        mma_f16(acc[mb][nb], a[mb][0], a[mb][1], a[mb][2], a[mb][3],
                                b0[nb], b1[nb]);
            }
            __syncthreads();
        }

        // Epilogue: bias, row L2 norm, store h (fp16), BN partials (fp32)
        float ssp[2][2] = {{0.f, 0.f}, {0.f, 0.f}};
#pragma unroll
        for (int mb = 0; mb < 2; mb++)
#pragma unroll
            for (int nb = 0; nb < 8; nb++) {
                acc[mb][nb][0] += bp[nb].x; acc[mb][nb][1] += bp[nb].y;
                acc[mb][nb][2] += bp[nb].x; acc[mb][nb][3] += bp[nb].y;
                ssp[mb][0] += acc[mb][nb][0] * acc[mb][nb][0] + acc[mb][nb][1] * acc[mb][nb][1];
                ssp[mb][1] += acc[mb][nb][2] * acc[mb][nb][2] + acc[mb][nb][3] * acc[mb][nb][3];
            }
#pragma unroll
        for (int mb = 0; mb < 2; mb++)
#pragma unroll
            for (int rs = 0; rs < 2; rs++) {
                ssp[mb][rs] += __shfl_xor_sync(0xffffffffu, ssp[mb][rs], 1);
                ssp[mb][rs] += __shfl_xor_sync(0xffffffffu, ssp[mb][rs], 2);
            }
        if (qk == 0) {
#pragma unroll
            for (int mb = 0; mb < 2; mb++)
#pragma unroll
                for (int rs = 0; rs < 2; rs++)
                    ssS[wn][wm * 32 + mb * 16 + rs * 8 + qr] = ssp[mb][rs];
        }
        __syncthreads();
        float inv[2][2];
#pragma unroll
        for (int mb = 0; mb < 2; mb++)
#pragma unroll
            for (int rs = 0; rs < 2; rs++) {
                int lr = wm * 32 + mb * 16 + rs * 8 + qr;
                float tot = ssS[0][lr] + ssS[1][lr];
                inv[mb][rs] = 1.f / fmaxf(sqrtf(tot), 1e-12f);
            }
#pragma unroll
        for (int mb = 0; mb < 2; mb++) {
            int lr0 = wm * 32 + mb * 16 + qr;
            int lr1 = lr0 + 8;
#pragma unroll
            for (int nb = 0; nb < 8; nb++) {
                int word = wn * 32 + nb * 4 + qk;   // col/2 within 64-word row
                if (lr0 < nrem) {
                    float vx = acc[mb][nb][0] * inv[mb][0];
                    float vy = acc[mb][nb][1] * inv[mb][0];
                    __half2 hv = __floats2half2_rn(vx, vy);
                    g_h16[(size_t)(base + lr0) * 64 + word] = *reinterpret_cast<u32*>(&hv);
                    s1[nb].x += vx; s1[nb].y += vy;
                    s2[nb].x += vx * vx; s2[nb].y += vy * vy;
                }
                if (lr1 < nrem) {
                    float vx = acc[mb][nb][2] * inv[mb][1];
                    float vy = acc[mb][nb][3] * inv[mb][1];
                    __half2 hv = __floats2half2_rn(vx, vy);
                    g_h16[(size_t)(base + lr1) * 64 + word] = *reinterpret_cast<u32*>(&hv);
                    s1[nb].x += vx; s1[nb].y += vy;
                    s2[nb].x += vx * vx; s2[nb].y += vy * vy;
                }
            }
        }
        __syncthreads();
    }

    // BN reduction
#pragma unroll
    for (int off = 4; off < 32; off <<= 1) {
#pragma unroll
        for (int nb = 0; nb < 8; nb++) {
            s1[nb].x += __shfl_xor_sync(0xffffffffu, s1[nb].x, off);
            s1[nb].y += __shfl_xor_sync(0xffffffffu, s1[nb].y, off);
            s2[nb].x += __shfl_xor_sync(0xffffffffu, s2[nb].x, off);
            s2[nb].y += __shfl_xor_sync(0xffffffffu, s2[nb].y, off);
        }
    }
    if (lane < 4) {
#pragma unroll
        for (int nb = 0; nb < 8; nb++) {
            int c = wn * 64 + nb * 8 + 2 * lane;
            bnstage[0][warp][c] = s1[nb].x; bnstage[0][warp][c + 1] = s1[nb].y;
            bnstage[1][warp][c] = s2[nb].x; bnstage[1][warp][c + 1] = s2[nb].y;
        }
    }
    __syncthreads();
    if (tid < 128) {
        int wsel = tid >> 6;
        float a0 = bnstage[0][wsel][tid] + bnstage[0][2 + wsel][tid];
        float a1 = bnstage[1][wsel][tid] + bnstage[1][2 + wsel][tid];
        atomicAdd(&g_bnsum[tid], a0);
        atomicAdd(&g_bnsq[tid], a1);
    }
}

__global__ void bn_finalize(const float* __restrict__ gamma, const float* __restrict__ beta, float invN) {
    int c = threadIdx.x;
    float mean = g_bnsum[c] * invN;
    float var = g_bnsq[c] * invN - mean * mean;
    float sc = gamma[c] * rsqrtf(var + 1e-5f);
    g_bnscale[c] = sc;
    g_bnshift[c] = beta[c] - mean * sc;
}

// ---------------------------------------------------------------------------
// GEMM2 (fp16 mma, 2-stage): out = L2norm_row(g_in @ W2 + b2l), 47 cols (48 pad)
// ---------------------------------------------------------------------------
__global__ void __launch_bounds__(128) sage_gemm2(
    const float* __restrict__ b2l, float* __restrict__ outp, int Nn)
{
    extern __shared__ u32 dyn[];
    u32* wSb = dyn;            // 2 * 768
    u32* iSb = dyn + 1536;     // 2 * 1280
    __shared__ float ssS[2][64];

    const int tid  = threadIdx.x;
    const int warp = tid >> 5, lane = tid & 31;
    const int wm = warp >> 1, wn = warp & 1;
    const int qr = lane >> 2, qk = lane & 3;

    float2 bp[3];
#pragma unroll
    for (int nb = 0; nb < 3; nb++) {
        int c = wn * 24 + nb * 8 + 2 * qk;
        bp[nb].x = (c < 47) ? b2l[c] : 0.f;
        bp[nb].y = (c + 1 < 47) ? b2l[c + 1] : 0.f;
    }

    for (int base = blockIdx.x * 64; base < Nn; base += gridDim.x * 64) {
        int nrem = min(64, Nn - base);

        float acc[2][3][4];
#pragma unroll
        for (int mb = 0; mb < 2; mb++)
#pragma unroll
            for (int nb = 0; nb < 3; nb++)
#pragma unroll
                for (int q = 0; q < 4; q++) acc[mb][nb][q] = 0.f;

        auto stage = [&](int kc, int buf) {
            u32* wdst = wSb + buf * 768;
            const u32* wsrc = g_wT2h + kc * 768;
            for (int i4 = tid; i4 < 192; i4 += 128) cpa16(&wdst[i4 * 4], &wsrc[i4 * 4]);
            u32* ib = iSb + buf * 1280;
            for (int i = tid; i < 256; i += 128) {
                int n = i >> 2, q = i & 3;
                void* dst = &ib[n * IWSTR + q * 4];
                const void* src = &g_in16[(size_t)(base + n) * 128 + kc * 16 + q * 4];
                if (n < nrem) cpa16(dst, src);
                else          cpa16_zero(dst, g_in16);
            }
        };

        stage(0, 0);
        cpa_commit();
        for (int kc = 0; kc < 8; kc++) {
            int cur = kc & 1;
            if (kc < 7) { stage(kc + 1, cur ^ 1); cpa_commit(); cpa_wait<1>(); }
            else        { cpa_wait<0>(); }
            __syncthreads();

            const u32* wS = wSb + cur * 768;
            const u32* inS = iSb + cur * 1280;
#pragma unroll
            for (int ks = 0; ks < 2; ks++) {
                u32 b0[3], b1[3];
                int wb0 = ks * 384 + wn * 192 + qr * 4 + qk;
#pragma unroll
                for (int nb = 0; nb < 3; nb++) {
                    b0[nb] = wS[wb0 + nb * 64];
                    b1[nb] = wS[wb0 + nb * 64 + 32];
                }
                u32 a[2][4];
#pragma unroll
                for (int mb = 0; mb < 2; mb++) {
                    int r0 = (wm * 32 + mb * 16 + qr) * IWSTR + ks * 8 + qk;
                    int r1 = r0 + 8 * IWSTR;
                    a[mb][0] = inS[r0];
                    a[mb][1] = inS[r1];
                    a[mb][2] = inS[r0 + 4];
                    a[mb][3] = inS[r1 + 4];
                }
#pragma unroll
                for (int mb = 0; mb < 2; mb++)
#pragma unroll
                    for (int nb = 0; nb < 3; nb++)
                        mma_f16(acc[mb][nb], a[mb][0], a[mb][1], a[mb][2], a[mb][3],
                                b0[nb], b1[nb]);
            }
            __syncthreads();
        }

        float ssp[2][2] = {{0.f, 0.f}, {0.f, 0.f}};
#pragma unroll
        for (int mb = 0; mb < 2; mb++)
#pragma unroll
            for (int nb = 0; nb < 3; nb++) {
                acc[mb][nb][0] += bp[nb].x; acc[mb][nb][1] += bp[nb].y;
                acc[mb][nb][2] += bp[nb].x; acc[mb][nb][3] += bp[nb].y;
                ssp[mb][0] += acc[mb][nb][0] * acc[mb][nb][0] + acc[mb][nb][1] * acc[mb][nb][1];
                ssp[mb][1] += acc[mb][nb][2] * acc[mb][nb][2] + acc[mb][nb][3] * acc[mb][nb][3];
            }
#pragma unroll
        for (int mb = 0; mb < 2; mb++)
#pragma unroll
            for (int rs = 0; rs < 2; rs++) {
                ssp[mb][rs] += __shfl_xor_sync(0xffffffffu, ssp[mb][rs], 1);
                ssp[mb][rs] += __shfl_xor_sync(0xffffffffu, ssp[mb][rs], 2);
            }
        if (qk == 0) {
#pragma unroll
            for (int mb = 0; mb < 2; mb++)
#pragma unroll
                for (int rs = 0; rs < 2; rs++)
                    ssS[wn][wm * 32 + mb * 16 + rs * 8 + qr] = ssp[mb][rs];
        }
        __syncthreads();
        float inv[2][2];
#pragma unroll
        for (int mb = 0; mb < 2; mb++)
#pragma unroll
            for (int rs = 0; rs < 2; rs++) {
                int lr = wm * 32 + mb * 16 + rs * 8 + qr;
                float tot = ssS[0][lr] + ssS[1][lr];
                inv[mb][rs] = 1.f / fmaxf(sqrtf(tot), 1e-12f);
            }
#pragma unroll
        for (int mb = 0; mb < 2; mb++) {
            int lr0 = wm * 32 + mb * 16 + qr;
            int lr1 = lr0 + 8;
#pragma unroll
            for (int nb = 0; nb < 3; nb++) {
                int c0 = wn * 24 + nb * 8 + 2 * qk;
                if (lr0 < nrem) {
                    size_t o = (size_t)(base + lr0) * 47;
                    if (c0 < 47)     outp[o + c0]     = acc[mb][nb][0] * inv[mb][0];
                    if (c0 + 1 < 47) outp[o + c0 + 1] = acc[mb][nb][1] * inv[mb][0];
                }
                if (lr1 < nrem) {
                    size_t o = (size_t)(base + lr1) * 47;
                    if (c0 < 47)     outp[o + c0]     = acc[mb][nb][2] * inv[mb][1];
                    if (c0 + 1 < 47) outp[o + c0 + 1] = acc[mb][nb][3] * inv[mb][1];
                }
            }
        }
        __syncthreads();
    }
}

// ---------------------------------------------------------------------------
extern "C" void kernel_launch(void* const* d_in, const int* in_sizes, int n_in,
                              void* d_out, int out_size) {
    const float* x     = (const float*)d_in[0];
    const void*  ei    = d_in[1];
    const float* w1l   = (const float*)d_in[2];
    const float* b1l   = (const float*)d_in[3];
    const float* w1r   = (const float*)d_in[4];
    const float* gamma = (const float*)d_in[5];
    const float* beta  = (const float*)d_in[6];
    const float* w2l   = (const float*)d_in[7];
    const float* b2l   = (const float*)d_in[8];
    const float* w2r   = (const float*)d_in[9];
    int Nn = in_sizes[0] / 128;
    int E  = in_sizes[1] / 2;

    int gb = (Nn + 63) / 64;
    int smem1 = (2 * 2048 + 2 * 1280) * 4;   // 26624 B
    int smem2 = (2 * 768 + 2 * 1280) * 4;    // 16384 B

    detect_ei<<<1, 32>>>(ei, Nn);
    prep_all<<<128, 256>>>(w1l, w1r, w2l, w2r, Nn);
    convert_x<<<1024, 256>>>((const float4*)x, Nn * 32);
    build_adj<<<(E + 255) / 256, 256>>>(ei, E, Nn);
    gather_mean<<<2048, 256>>>(0, Nn);
    sage_gemm1<<<gb, 128, smem1>>>(b1l, Nn);
    bn_finalize<<<1, 128>>>(gamma, beta, 1.0f / (float)Nn);
    gather_mean<<<2048, 256>>>(1, Nn);
    sage_gemm2<<<gb, 128, smem2>>>(b2l, (float*)d_out, Nn);
}